// round 1
// baseline (speedup 1.0000x reference)
#include <cuda_runtime.h>
#include <cuda_bf16.h>

// ---------------------------------------------------------------------------
// Scratch buffers (device globals — no allocation allowed)
// ---------------------------------------------------------------------------
__device__ float g_encb1[16 * 128 * 128 * 128]; // after conv1  [16,128,128,128]
__device__ float g_encb [16 * 128 * 64 * 64];   // after conv2  [16,128,64,64]
__device__ float g_enct [16 * 128 * 32 * 32];   // after conv3  [16,128,32,32]
__device__ float g_dect [16 * 64 * 64 * 64];    // decoder_top out
__device__ float g_upt  [16 * 64 * 64 * 64];    // upsample_t out
__device__ float g_h    [16 * 64 * 128 * 128];  // decoder_bottom hidden
__device__ float g_normt[512];
__device__ float g_normb[512];
__device__ float g_acc[2];                      // diff_t_sum, diff_b_sum

#define CHNK 8

// ---------------------------------------------------------------------------
// init: codebook norms + zero loss accumulators
// ---------------------------------------------------------------------------
__global__ void init_kernel(const float* __restrict__ et, const float* __restrict__ eb,
                            float* __restrict__ nt, float* __restrict__ nb,
                            float* __restrict__ acc) {
    int k = threadIdx.x; // 512 threads
    float st = 0.f, sb = 0.f;
#pragma unroll
    for (int d = 0; d < 64; d++) {
        float a = et[d * 512 + k]; st = fmaf(a, a, st);
        float b = eb[d * 512 + k]; sb = fmaf(b, b, sb);
    }
    nt[k] = st;
    nb[k] = sb;
    if (k < 2) acc[k] = 0.f;
}

// ---------------------------------------------------------------------------
// 4x4 stride-2 pad-1 conv (+ optional relu).  NCHW in/out, OIHW weights.
// Block: 256 thr = 8x8 pixels x 4 lanes; each thread: 8 output channels.
// Grid: (Wout/8, Hout/8, N * Cout/32)
// ---------------------------------------------------------------------------
template <bool RELU>
__global__ __launch_bounds__(256) void conv4x4s2_kernel(
    const float* __restrict__ in, const float* __restrict__ w,
    const float* __restrict__ bias, float* __restrict__ out,
    int N, int Cin, int Cout, int Hin, int Win) {
    const int Hout = Hin >> 1, Wout = Win >> 1;
    const int tid = threadIdx.x;
    const int lane4 = tid & 3;
    const int pix = tid >> 2;
    const int px = pix & 7, py = pix >> 3;
    const int ox0 = blockIdx.x << 3, oy0 = blockIdx.y << 3;
    const int cog = Cout >> 5;
    const int n = blockIdx.z / cog;
    const int co0 = (blockIdx.z % cog) << 5;

    __shared__ float s_in[CHNK][18][18];
    __shared__ float s_w[CHNK][16][36]; // padded: aligned float4, few conflicts

    float acc[8];
#pragma unroll
    for (int i = 0; i < 8; i++) acc[i] = 0.f;

    const int iyb = 2 * oy0 - 1, ixb = 2 * ox0 - 1;

    for (int ci0 = 0; ci0 < Cin; ci0 += CHNK) {
        const int cc = min(CHNK, Cin - ci0);
        // input tile cc x 18 x 18 (zero padded)
        for (int idx = tid; idx < cc * 324; idx += 256) {
            int c = idx / 324, r = idx - c * 324;
            int yy = r / 18, xx = r - yy * 18;
            int iy = iyb + yy, ix = ixb + xx;
            float v = 0.f;
            if ((unsigned)iy < (unsigned)Hin && (unsigned)ix < (unsigned)Win)
                v = in[((n * Cin + ci0 + c) * Hin + iy) * Win + ix];
            s_in[c][yy][xx] = v;
        }
        // weights: coalesced global read, layout s_w[c][kk][co]
        const int cseg = cc * 16;
        for (int idx = tid; idx < cc * 512; idx += 256) {
            int co = idx / cseg;
            int r = idx - co * cseg; // r = c*16 + kk
            int c = r >> 4, kk = r & 15;
            s_w[c][kk][co] = w[(co0 + co) * Cin * 16 + ci0 * 16 + r];
        }
        __syncthreads();
        for (int c = 0; c < cc; c++) {
#pragma unroll
            for (int kk = 0; kk < 16; kk++) {
                const float v = s_in[c][2 * py + (kk >> 2)][2 * px + (kk & 3)];
                const float* wp = &s_w[c][kk][lane4 * 8];
                const float4 w0 = *(const float4*)(wp);
                const float4 w1 = *(const float4*)(wp + 4);
                acc[0] = fmaf(v, w0.x, acc[0]);
                acc[1] = fmaf(v, w0.y, acc[1]);
                acc[2] = fmaf(v, w0.z, acc[2]);
                acc[3] = fmaf(v, w0.w, acc[3]);
                acc[4] = fmaf(v, w1.x, acc[4]);
                acc[5] = fmaf(v, w1.y, acc[5]);
                acc[6] = fmaf(v, w1.z, acc[6]);
                acc[7] = fmaf(v, w1.w, acc[7]);
            }
        }
        __syncthreads();
    }
    const int oy = oy0 + py, ox = ox0 + px;
#pragma unroll
    for (int j = 0; j < 8; j++) {
        const int co = co0 + lane4 * 8 + j;
        float r = acc[j] + bias[co];
        if (RELU) r = fmaxf(r, 0.f);
        out[((n * Cout + co) * Hout + oy) * Wout + ox] = r;
    }
}

// ---------------------------------------------------------------------------
// 4x4 stride-2 pad-1 conv-transpose (+ optional relu).
// Weights torch layout [Cin][Cout][4][4]. Input may be split across 2 tensors
// at channel CA (concat fusion). Block: 8x8 output pixels x 4 lanes, 32 couts.
// out[oy] receives in[iy] with oy = 2*iy + ky - 1.
// ---------------------------------------------------------------------------
template <bool RELU>
__global__ __launch_bounds__(256) void convT4x4_kernel(
    const float* __restrict__ inA, const float* __restrict__ inB, int CA,
    const float* __restrict__ w, const float* __restrict__ bias,
    float* __restrict__ out, int N, int Cin, int Cout, int Hin, int Win) {
    const int Hout = Hin << 1, Wout = Win << 1;
    const int tid = threadIdx.x;
    const int lane4 = tid & 3;
    const int pix = tid >> 2;
    const int px = pix & 7, py = pix >> 3;
    const int ox0 = blockIdx.x << 3, oy0 = blockIdx.y << 3;
    const int cog = Cout >> 5;
    const int n = blockIdx.z / cog;
    const int co0 = (blockIdx.z % cog) << 5;
    const int CB = Cin - CA;

    __shared__ float s_in[CHNK][6][6];
    __shared__ float s_w[CHNK][16][36];

    float acc[8];
#pragma unroll
    for (int i = 0; i < 8; i++) acc[i] = 0.f;

    const int iy0 = (oy0 >> 1) - 1, ix0 = (ox0 >> 1) - 1;
    const int oy = oy0 + py, ox = ox0 + px;
    const int pary = (oy + 1) & 1, parx = (ox + 1) & 1;
    const int ryl = ((oy + 1 - pary) >> 1) - iy0; // in [1,5]
    const int rxl = ((ox + 1 - parx) >> 1) - ix0;

    for (int ci0 = 0; ci0 < Cin; ci0 += CHNK) {
        const int cc = min(CHNK, Cin - ci0);
        for (int idx = tid; idx < cc * 36; idx += 256) {
            int c = idx / 36, r = idx - c * 36;
            int yy = r / 6, xx = r - yy * 6;
            int iy = iy0 + yy, ix = ix0 + xx;
            int ci = ci0 + c;
            float v = 0.f;
            if ((unsigned)iy < (unsigned)Hin && (unsigned)ix < (unsigned)Win) {
                if (ci < CA)
                    v = inA[((n * CA + ci) * Hin + iy) * Win + ix];
                else
                    v = inB[((n * CB + (ci - CA)) * Hin + iy) * Win + ix];
            }
            s_in[c][yy][xx] = v;
        }
        for (int idx = tid; idx < cc * 512; idx += 256) {
            int c = idx >> 9, r = idx & 511; // r = co*16 + kk
            int co = r >> 4, kk = r & 15;
            s_w[c][kk][co] = w[(ci0 + c) * Cout * 16 + co0 * 16 + r];
        }
        __syncthreads();
        for (int c = 0; c < cc; c++) {
#pragma unroll
            for (int dy = 0; dy < 2; dy++) {
                const int ky = pary + 2 * dy;
                const int row = ryl - dy;
#pragma unroll
                for (int dx = 0; dx < 2; dx++) {
                    const int kx = parx + 2 * dx;
                    const int col = rxl - dx;
                    const float v = s_in[c][row][col];
                    const float* wp = &s_w[c][ky * 4 + kx][lane4 * 8];
                    const float4 w0 = *(const float4*)(wp);
                    const float4 w1 = *(const float4*)(wp + 4);
                    acc[0] = fmaf(v, w0.x, acc[0]);
                    acc[1] = fmaf(v, w0.y, acc[1]);
                    acc[2] = fmaf(v, w0.z, acc[2]);
                    acc[3] = fmaf(v, w0.w, acc[3]);
                    acc[4] = fmaf(v, w1.x, acc[4]);
                    acc[5] = fmaf(v, w1.y, acc[5]);
                    acc[6] = fmaf(v, w1.z, acc[6]);
                    acc[7] = fmaf(v, w1.w, acc[7]);
                }
            }
        }
        __syncthreads();
    }
#pragma unroll
    for (int j = 0; j < 8; j++) {
        const int co = co0 + lane4 * 8 + j;
        float r = acc[j] + bias[co];
        if (RELU) r = fmaxf(r, 0.f);
        out[((n * Cout + co) * Hout + oy) * Wout + ox] = r;
    }
}

// ---------------------------------------------------------------------------
// ConvT for small Cout (=3): block = 16x16 output pixels, each thread 3 couts.
// ---------------------------------------------------------------------------
__global__ __launch_bounds__(256) void convT4x4_small_kernel(
    const float* __restrict__ in, const float* __restrict__ w,
    const float* __restrict__ bias, float* __restrict__ out,
    int N, int Cin, int Hin, int Win) {
    const int Cout = 3;
    const int Hout = Hin << 1, Wout = Win << 1;
    const int tid = threadIdx.x;
    const int px = tid & 15, py = tid >> 4;
    const int ox0 = blockIdx.x << 4, oy0 = blockIdx.y << 4;
    const int n = blockIdx.z;

    __shared__ float s_in[CHNK][10][10];
    __shared__ float s_w[CHNK][16][4];

    float acc0 = 0.f, acc1 = 0.f, acc2 = 0.f;

    const int iy0 = (oy0 >> 1) - 1, ix0 = (ox0 >> 1) - 1;
    const int oy = oy0 + py, ox = ox0 + px;
    const int pary = (oy + 1) & 1, parx = (ox + 1) & 1;
    const int ryl = ((oy + 1 - pary) >> 1) - iy0; // in [1,9]
    const int rxl = ((ox + 1 - parx) >> 1) - ix0;

    for (int ci0 = 0; ci0 < Cin; ci0 += CHNK) {
        const int cc = min(CHNK, Cin - ci0);
        for (int idx = tid; idx < cc * 100; idx += 256) {
            int c = idx / 100, r = idx - c * 100;
            int yy = r / 10, xx = r - yy * 10;
            int iy = iy0 + yy, ix = ix0 + xx;
            float v = 0.f;
            if ((unsigned)iy < (unsigned)Hin && (unsigned)ix < (unsigned)Win)
                v = in[((n * Cin + ci0 + c) * Hin + iy) * Win + ix];
            s_in[c][yy][xx] = v;
        }
        for (int idx = tid; idx < cc * 48; idx += 256) {
            int c = idx / 48, r = idx - c * 48; // r = co*16 + kk
            int co = r >> 4, kk = r & 15;
            s_w[c][kk][co] = w[(ci0 + c) * Cout * 16 + r];
        }
        __syncthreads();
        for (int c = 0; c < cc; c++) {
#pragma unroll
            for (int dy = 0; dy < 2; dy++) {
                const int ky = pary + 2 * dy;
                const int row = ryl - dy;
#pragma unroll
                for (int dx = 0; dx < 2; dx++) {
                    const int kx = parx + 2 * dx;
                    const int col = rxl - dx;
                    const float v = s_in[c][row][col];
                    const int kk = ky * 4 + kx;
                    acc0 = fmaf(v, s_w[c][kk][0], acc0);
                    acc1 = fmaf(v, s_w[c][kk][1], acc1);
                    acc2 = fmaf(v, s_w[c][kk][2], acc2);
                }
            }
        }
        __syncthreads();
    }
    out[((n * 3 + 0) * Hout + oy) * Wout + ox] = acc0 + bias[0];
    out[((n * 3 + 1) * Hout + oy) * Wout + ox] = acc1 + bias[1];
    out[((n * 3 + 2) * Hout + oy) * Wout + ox] = acc2 + bias[2];
}

// ---------------------------------------------------------------------------
// Fused 1x1 conv (Cin -> 64, optional channel-concat input) + vector quantize.
// One thread per pixel; f[64] in registers. Block 256.
// Writes: quant (NCHW, value = selected codebook column), index (as float),
// and atomically accumulates sum((q - z)^2).
// ---------------------------------------------------------------------------
__global__ __launch_bounds__(256) void conv1x1_quantize_kernel(
    const float* __restrict__ inA, const float* __restrict__ inB, int CA, int CB,
    const float* __restrict__ w, const float* __restrict__ b,
    const float* __restrict__ embed, const float* __restrict__ norms,
    float* __restrict__ qout, float* __restrict__ idout, float* __restrict__ acc,
    int HW) {
    const int tid = threadIdx.x;
    const int v = blockIdx.x * 256 + tid;
    const int n = v / HW, hw = v - n * HW;
    const int Cin = CA + CB;

    __shared__ float s_w[16][68];
    __shared__ float s_e[128][68];
    __shared__ float s_n[128];

    float f[64];
#pragma unroll
    for (int i = 0; i < 64; i++) f[i] = 0.f;

    // ---- 1x1 conv: f[co] = sum_ci in[ci] * w[co][ci] ----
    for (int ci0 = 0; ci0 < Cin; ci0 += 16) {
        for (int idx = tid; idx < 1024; idx += 256) {
            int c = idx & 15, co = idx >> 4;
            s_w[c][co] = w[co * Cin + ci0 + c];
        }
        __syncthreads();
#pragma unroll 4
        for (int c = 0; c < 16; c++) {
            const int ci = ci0 + c;
            float val;
            if (ci < CA)
                val = inA[(n * CA + ci) * HW + hw];
            else
                val = inB[(n * CB + (ci - CA)) * HW + hw];
            const float4* wr = (const float4*)s_w[c];
#pragma unroll
            for (int j = 0; j < 16; j++) {
                const float4 wv = wr[j];
                f[4 * j + 0] = fmaf(val, wv.x, f[4 * j + 0]);
                f[4 * j + 1] = fmaf(val, wv.y, f[4 * j + 1]);
                f[4 * j + 2] = fmaf(val, wv.z, f[4 * j + 2]);
                f[4 * j + 3] = fmaf(val, wv.w, f[4 * j + 3]);
            }
        }
        __syncthreads();
    }
    // bias
    const float4* b4 = (const float4*)b;
#pragma unroll
    for (int j = 0; j < 16; j++) {
        const float4 bv = b4[j];
        f[4 * j + 0] += bv.x;
        f[4 * j + 1] += bv.y;
        f[4 * j + 2] += bv.z;
        f[4 * j + 3] += bv.w;
    }

    // ---- argmin_k ( ||e_k||^2 - 2 f.e_k ) ----
    float best = 3.4e38f;
    int bid = 0;
    for (int k0 = 0; k0 < 512; k0 += 128) {
        for (int idx = tid; idx < 8192; idx += 256) {
            int d = idx >> 7, k = idx & 127;
            s_e[k][d] = embed[d * 512 + k0 + k];
        }
        if (tid < 128) s_n[tid] = norms[k0 + tid];
        __syncthreads();
        for (int k = 0; k < 128; k++) {
            float d0 = 0.f, d1 = 0.f, d2 = 0.f, d3 = 0.f;
            const float4* er = (const float4*)s_e[k];
#pragma unroll
            for (int j = 0; j < 16; j++) {
                const float4 e = er[j];
                d0 = fmaf(f[4 * j + 0], e.x, d0);
                d1 = fmaf(f[4 * j + 1], e.y, d1);
                d2 = fmaf(f[4 * j + 2], e.z, d2);
                d3 = fmaf(f[4 * j + 3], e.w, d3);
            }
            const float sc = s_n[k] - 2.f * ((d0 + d1) + (d2 + d3));
            if (sc < best) { best = sc; bid = k0 + k; }
        }
        __syncthreads();
    }

    // ---- emit quantized vector, index, commitment-loss partial ----
    float lsum = 0.f;
#pragma unroll
    for (int d = 0; d < 64; d++) {
        const float q = __ldg(&embed[d * 512 + bid]);
        const float df = q - f[d];
        lsum = fmaf(df, df, lsum);
        qout[(n * 64 + d) * HW + hw] = q;
    }
    idout[v] = (float)bid;
#pragma unroll
    for (int o = 16; o > 0; o >>= 1) lsum += __shfl_down_sync(0xffffffffu, lsum, o);
    if ((tid & 31) == 0) atomicAdd(acc, lsum);
}

__global__ void finalize_loss_kernel(const float* __restrict__ acc, float* __restrict__ o) {
    o[0] = acc[0] * (1.f / 1048576.f) + acc[1] * (1.f / 4194304.f);
}

// ---------------------------------------------------------------------------
// host launcher
// ---------------------------------------------------------------------------
extern "C" void kernel_launch(void* const* d_in, const int* in_sizes, int n_in,
                              void* d_out, int out_size) {
    (void)in_sizes; (void)n_in; (void)out_size;
    const float* x       = (const float*)d_in[0];
    const float* wb1     = (const float*)d_in[1];
    const float* bb1     = (const float*)d_in[2];
    const float* wb2     = (const float*)d_in[3];
    const float* bb2     = (const float*)d_in[4];
    const float* wt1     = (const float*)d_in[5];
    const float* bt1     = (const float*)d_in[6];
    const float* wqt     = (const float*)d_in[7];
    const float* bqt     = (const float*)d_in[8];
    const float* embed_t = (const float*)d_in[9];
    const float* wdt     = (const float*)d_in[10];
    const float* bdt     = (const float*)d_in[11];
    const float* wqb     = (const float*)d_in[12];
    const float* bqb     = (const float*)d_in[13];
    const float* embed_b = (const float*)d_in[14];
    const float* wup     = (const float*)d_in[15];
    const float* bup     = (const float*)d_in[16];
    const float* wd1     = (const float*)d_in[17];
    const float* bd1     = (const float*)d_in[18];
    const float* wd2     = (const float*)d_in[19];
    const float* bd2     = (const float*)d_in[20];

    float* out    = (float*)d_out;
    float* o_xhat = out;                 // 16*3*256*256   = 3145728
    float* o_qt   = out + 3145728;       // 16*64*32*32    = 1048576
    float* o_qb   = out + 4194304;       // 16*64*64*64    = 4194304
    float* o_loss = out + 8388608;       // 1
    float* o_idt  = out + 8388609;       // 16*32*32       = 16384
    float* o_idb  = out + 8404993;       // 16*64*64       = 65536

    float *encb1, *encb, *enct, *dect, *upt, *h, *normt, *normb, *acc;
    cudaGetSymbolAddress((void**)&encb1, g_encb1);
    cudaGetSymbolAddress((void**)&encb,  g_encb);
    cudaGetSymbolAddress((void**)&enct,  g_enct);
    cudaGetSymbolAddress((void**)&dect,  g_dect);
    cudaGetSymbolAddress((void**)&upt,   g_upt);
    cudaGetSymbolAddress((void**)&h,     g_h);
    cudaGetSymbolAddress((void**)&normt, g_normt);
    cudaGetSymbolAddress((void**)&normb, g_normb);
    cudaGetSymbolAddress((void**)&acc,   g_acc);

    init_kernel<<<1, 512>>>(embed_t, embed_b, normt, normb, acc);

    // ---- encoder ----
    conv4x4s2_kernel<true><<<dim3(16, 16, 16 * 4), 256>>>(x, wb1, bb1, encb1, 16, 3, 128, 256, 256);
    conv4x4s2_kernel<true><<<dim3(8, 8, 16 * 4), 256>>>(encb1, wb2, bb2, encb, 16, 128, 128, 128, 128);
    conv4x4s2_kernel<true><<<dim3(4, 4, 16 * 4), 256>>>(encb, wt1, bt1, enct, 16, 128, 128, 64, 64);

    // ---- top quantize ----
    conv1x1_quantize_kernel<<<16384 / 256, 256>>>(enct, enct, 128, 0, wqt, bqt,
                                                  embed_t, normt, o_qt, o_idt, acc + 0, 1024);

    // ---- decoder_top, bottom quantize ----
    convT4x4_kernel<false><<<dim3(8, 8, 16 * 2), 256>>>(o_qt, o_qt, 64, wdt, bdt, dect, 16, 64, 64, 32, 32);
    conv1x1_quantize_kernel<<<65536 / 256, 256>>>(dect, encb, 64, 128, wqb, bqb,
                                                  embed_b, normb, o_qb, o_idb, acc + 1, 4096);

    // ---- decode ----
    convT4x4_kernel<false><<<dim3(8, 8, 16 * 2), 256>>>(o_qt, o_qt, 64, wup, bup, upt, 16, 64, 64, 32, 32);
    convT4x4_kernel<true><<<dim3(16, 16, 16 * 2), 256>>>(upt, o_qb, 64, wd1, bd1, h, 16, 128, 64, 64, 64);
    convT4x4_small_kernel<<<dim3(16, 16, 16), 256>>>(h, wd2, bd2, o_xhat, 16, 64, 128, 128);

    finalize_loss_kernel<<<1, 1>>>(acc, o_loss);
}

// round 2
// speedup vs baseline: 1.2915x; 1.2915x over previous
#include <cuda_runtime.h>
#include <cuda_bf16.h>

// ---------------------------------------------------------------------------
// Scratch buffers (device globals — no allocation allowed)
// ---------------------------------------------------------------------------
__device__ float g_encb1[16 * 128 * 128 * 128]; // after conv1  [16,128,128,128]
__device__ float g_encb [16 * 128 * 64 * 64];   // after conv2  [16,128,64,64]
__device__ float g_enct [16 * 128 * 32 * 32];   // after conv3  [16,128,32,32]
__device__ float g_dect [16 * 64 * 64 * 64];    // decoder_top out
__device__ float g_upt  [16 * 64 * 64 * 64];    // upsample_t out
__device__ float g_h    [16 * 64 * 128 * 128];  // decoder_bottom hidden
__device__ float g_normt[512];
__device__ float g_normb[512];
__device__ float g_acc[2];                      // diff_t_sum, diff_b_sum

// ---------------------------------------------------------------------------
// init: codebook norms + zero loss accumulators
// ---------------------------------------------------------------------------
__global__ void init_kernel(const float* __restrict__ et, const float* __restrict__ eb,
                            float* __restrict__ nt, float* __restrict__ nb,
                            float* __restrict__ acc) {
    int k = threadIdx.x; // 512 threads
    float st = 0.f, sb = 0.f;
#pragma unroll
    for (int d = 0; d < 64; d++) {
        float a = et[d * 512 + k]; st = fmaf(a, a, st);
        float b = eb[d * 512 + k]; sb = fmaf(b, b, sb);
    }
    nt[k] = st;
    nb[k] = sb;
    if (k < 2) acc[k] = 0.f;
}

// ---------------------------------------------------------------------------
// 4x4 stride-2 pad-1 conv (+ optional relu).  NCHW in/out, OIHW weights.
// Block: 256 thr = 8x8 superpixels (2x2 out pixels each) x 4 channel lanes.
// Each thread: 2x2 pixels x 8 output channels = 32 accumulators.
// Output tile 16x16.  Grid: (Wout/16, Hout/16, N * Cout/32)
// ---------------------------------------------------------------------------
#define CCHNK 4
template <bool RELU>
__global__ __launch_bounds__(256) void conv4x4s2_kernel(
    const float* __restrict__ in, const float* __restrict__ w,
    const float* __restrict__ bias, float* __restrict__ out,
    int N, int Cin, int Cout, int Hin, int Win) {
    const int Hout = Hin >> 1, Wout = Win >> 1;
    const int tid = threadIdx.x;
    const int lane4 = tid & 3;
    const int sp = tid >> 2;
    const int sx = sp & 7, sy = sp >> 3;
    const int ox0 = blockIdx.x << 4, oy0 = blockIdx.y << 4;
    const int cog = Cout >> 5;
    const int n = blockIdx.z / cog;
    const int co0 = (blockIdx.z % cog) << 5;

    __shared__ float s_in[CCHNK][34][34];
    __shared__ float s_w[CCHNK][16][36];

    float acc[4][8];
#pragma unroll
    for (int p = 0; p < 4; p++)
#pragma unroll
        for (int j = 0; j < 8; j++) acc[p][j] = 0.f;

    const int iyb = 2 * oy0 - 1, ixb = 2 * ox0 - 1;
    const int by = 4 * sy, bx = 4 * sx;

    for (int ci0 = 0; ci0 < Cin; ci0 += CCHNK) {
        const int cc = min(CCHNK, Cin - ci0);
        // input tile cc x 34 x 34 (zero padded)
        for (int idx = tid; idx < cc * 1156; idx += 256) {
            int c = idx / 1156, r = idx - c * 1156;
            int yy = r / 34, xx = r - yy * 34;
            int iy = iyb + yy, ix = ixb + xx;
            float v = 0.f;
            if ((unsigned)iy < (unsigned)Hin && (unsigned)ix < (unsigned)Win)
                v = in[((n * Cin + ci0 + c) * Hin + iy) * Win + ix];
            s_in[c][yy][xx] = v;
        }
        // weights: coalesced global read, layout s_w[c][kk][co]
        const int cseg = cc * 16;
        for (int idx = tid; idx < cc * 512; idx += 256) {
            int co = idx / cseg;
            int r = idx - co * cseg; // r = c*16 + kk
            int c = r >> 4, kk = r & 15;
            s_w[c][kk][co] = w[(co0 + co) * Cin * 16 + ci0 * 16 + r];
        }
        __syncthreads();
        for (int c = 0; c < cc; c++) {
#pragma unroll
            for (int kk = 0; kk < 16; kk++) {
                const int ky = kk >> 2, kx = kk & 3;
                const float v00 = s_in[c][by + ky][bx + kx];
                const float v01 = s_in[c][by + ky][bx + kx + 2];
                const float v10 = s_in[c][by + ky + 2][bx + kx];
                const float v11 = s_in[c][by + ky + 2][bx + kx + 2];
                const float* wp = &s_w[c][kk][lane4 * 8];
                const float4 w0 = *(const float4*)(wp);
                const float4 w1 = *(const float4*)(wp + 4);
                const float wv[8] = {w0.x, w0.y, w0.z, w0.w, w1.x, w1.y, w1.z, w1.w};
#pragma unroll
                for (int j = 0; j < 8; j++) {
                    acc[0][j] = fmaf(v00, wv[j], acc[0][j]);
                    acc[1][j] = fmaf(v01, wv[j], acc[1][j]);
                    acc[2][j] = fmaf(v10, wv[j], acc[2][j]);
                    acc[3][j] = fmaf(v11, wv[j], acc[3][j]);
                }
            }
        }
        __syncthreads();
    }
#pragma unroll
    for (int dy = 0; dy < 2; dy++)
#pragma unroll
        for (int dx = 0; dx < 2; dx++) {
            const int oy = oy0 + 2 * sy + dy, ox = ox0 + 2 * sx + dx;
#pragma unroll
            for (int j = 0; j < 8; j++) {
                const int co = co0 + lane4 * 8 + j;
                float r = acc[dy * 2 + dx][j] + bias[co];
                if (RELU) r = fmaxf(r, 0.f);
                out[((n * Cout + co) * Hout + oy) * Wout + ox] = r;
            }
        }
}

// ---------------------------------------------------------------------------
// 4x4 stride-2 pad-1 conv-transpose (+ optional relu).
// Weights torch layout [Cin][Cout][4][4]. Input may be split across 2 tensors
// at channel CA (concat fusion). 2x2 superpixel x 8 channels per thread.
// Output tile 16x16. oy = 2*iy + ky - 1  =>  iy = (oy+1-ky)/2.
// ---------------------------------------------------------------------------
#define TCHNK 8
template <bool RELU>
__global__ __launch_bounds__(256) void convT4x4_kernel(
    const float* __restrict__ inA, const float* __restrict__ inB, int CA,
    const float* __restrict__ w, const float* __restrict__ bias,
    float* __restrict__ out, int N, int Cin, int Cout, int Hin, int Win) {
    const int Hout = Hin << 1, Wout = Win << 1;
    const int tid = threadIdx.x;
    const int lane4 = tid & 3;
    const int sp = tid >> 2;
    const int sx = sp & 7, sy = sp >> 3;
    const int ox0 = blockIdx.x << 4, oy0 = blockIdx.y << 4;
    const int cog = Cout >> 5;
    const int n = blockIdx.z / cog;
    const int co0 = (blockIdx.z % cog) << 5;
    const int CB = Cin - CA;

    __shared__ float s_in[TCHNK][10][10];
    __shared__ float s_w[TCHNK][16][36];

    float acc[4][8];
#pragma unroll
    for (int p = 0; p < 4; p++)
#pragma unroll
        for (int j = 0; j < 8; j++) acc[p][j] = 0.f;

    const int iy0 = (oy0 >> 1) - 1, ix0 = (ox0 >> 1) - 1;

    for (int ci0 = 0; ci0 < Cin; ci0 += TCHNK) {
        const int cc = min(TCHNK, Cin - ci0);
        for (int idx = tid; idx < cc * 100; idx += 256) {
            int c = idx / 100, r = idx - c * 100;
            int yy = r / 10, xx = r - yy * 10;
            int iy = iy0 + yy, ix = ix0 + xx;
            int ci = ci0 + c;
            float v = 0.f;
            if ((unsigned)iy < (unsigned)Hin && (unsigned)ix < (unsigned)Win) {
                if (ci < CA)
                    v = inA[((n * CA + ci) * Hin + iy) * Win + ix];
                else
                    v = inB[((n * CB + (ci - CA)) * Hin + iy) * Win + ix];
            }
            s_in[c][yy][xx] = v;
        }
        for (int idx = tid; idx < cc * 512; idx += 256) {
            int c = idx >> 9, r = idx & 511; // r = co*16 + kk
            int co = r >> 4, kk = r & 15;
            s_w[c][kk][co] = w[(ci0 + c) * Cout * 16 + co0 * 16 + r];
        }
        __syncthreads();
        for (int c = 0; c < cc; c++) {
            float vin[3][3];
#pragma unroll
            for (int i = 0; i < 3; i++)
#pragma unroll
                for (int j2 = 0; j2 < 3; j2++) vin[i][j2] = s_in[c][sy + i][sx + j2];
#pragma unroll
            for (int kk = 0; kk < 16; kk++) {
                const int ky = kk >> 2, kx = kk & 3;
                // ky odd -> even output row (dy=0); ky even -> dy=1
                const int dy = (ky & 1) ? 0 : 1;
                const int ry = (ky & 1) ? (1 - ((ky - 1) >> 1)) : (2 - (ky >> 1));
                const int dx = (kx & 1) ? 0 : 1;
                const int rx = (kx & 1) ? (1 - ((kx - 1) >> 1)) : (2 - (kx >> 1));
                const float v = vin[ry][rx];
                const float* wp = &s_w[c][kk][lane4 * 8];
                const float4 w0 = *(const float4*)(wp);
                const float4 w1 = *(const float4*)(wp + 4);
                float* a = acc[dy * 2 + dx];
                a[0] = fmaf(v, w0.x, a[0]);
                a[1] = fmaf(v, w0.y, a[1]);
                a[2] = fmaf(v, w0.z, a[2]);
                a[3] = fmaf(v, w0.w, a[3]);
                a[4] = fmaf(v, w1.x, a[4]);
                a[5] = fmaf(v, w1.y, a[5]);
                a[6] = fmaf(v, w1.z, a[6]);
                a[7] = fmaf(v, w1.w, a[7]);
            }
        }
        __syncthreads();
    }
#pragma unroll
    for (int dy = 0; dy < 2; dy++)
#pragma unroll
        for (int dx = 0; dx < 2; dx++) {
            const int oy = oy0 + 2 * sy + dy, ox = ox0 + 2 * sx + dx;
#pragma unroll
            for (int j = 0; j < 8; j++) {
                const int co = co0 + lane4 * 8 + j;
                float r = acc[dy * 2 + dx][j] + bias[co];
                if (RELU) r = fmaxf(r, 0.f);
                out[((n * Cout + co) * Hout + oy) * Wout + ox] = r;
            }
        }
}

// ---------------------------------------------------------------------------
// ConvT for small Cout (=3): 2x2 superpixel per thread, out tile 32x32.
// Block 256 = 16x16 superpixels.
// ---------------------------------------------------------------------------
__global__ __launch_bounds__(256) void convT4x4_small_kernel(
    const float* __restrict__ in, const float* __restrict__ w,
    const float* __restrict__ bias, float* __restrict__ out,
    int N, int Cin, int Hin, int Win) {
    const int Cout = 3;
    const int Hout = Hin << 1, Wout = Win << 1;
    const int tid = threadIdx.x;
    const int sx = tid & 15, sy = tid >> 4;
    const int ox0 = blockIdx.x << 5, oy0 = blockIdx.y << 5;
    const int n = blockIdx.z;

    __shared__ float s_in[TCHNK][18][18];
    __shared__ float s_w[TCHNK][16][4];

    float acc[4][3];
#pragma unroll
    for (int p = 0; p < 4; p++)
#pragma unroll
        for (int j = 0; j < 3; j++) acc[p][j] = 0.f;

    const int iy0 = (oy0 >> 1) - 1, ix0 = (ox0 >> 1) - 1;

    for (int ci0 = 0; ci0 < Cin; ci0 += TCHNK) {
        const int cc = min(TCHNK, Cin - ci0);
        for (int idx = tid; idx < cc * 324; idx += 256) {
            int c = idx / 324, r = idx - c * 324;
            int yy = r / 18, xx = r - yy * 18;
            int iy = iy0 + yy, ix = ix0 + xx;
            float v = 0.f;
            if ((unsigned)iy < (unsigned)Hin && (unsigned)ix < (unsigned)Win)
                v = in[((n * Cin + ci0 + c) * Hin + iy) * Win + ix];
            s_in[c][yy][xx] = v;
        }
        for (int idx = tid; idx < cc * 48; idx += 256) {
            int c = idx / 48, r = idx - c * 48; // r = co*16 + kk
            int co = r >> 4, kk = r & 15;
            s_w[c][kk][co] = w[(ci0 + c) * Cout * 16 + r];
        }
        __syncthreads();
        for (int c = 0; c < cc; c++) {
            float vin[3][3];
#pragma unroll
            for (int i = 0; i < 3; i++)
#pragma unroll
                for (int j2 = 0; j2 < 3; j2++) vin[i][j2] = s_in[c][sy + i][sx + j2];
#pragma unroll
            for (int kk = 0; kk < 16; kk++) {
                const int ky = kk >> 2, kx = kk & 3;
                const int dy = (ky & 1) ? 0 : 1;
                const int ry = (ky & 1) ? (1 - ((ky - 1) >> 1)) : (2 - (ky >> 1));
                const int dx = (kx & 1) ? 0 : 1;
                const int rx = (kx & 1) ? (1 - ((kx - 1) >> 1)) : (2 - (kx >> 1));
                const float v = vin[ry][rx];
                const float4 wv = *(const float4*)&s_w[c][kk][0];
                float* a = acc[dy * 2 + dx];
                a[0] = fmaf(v, wv.x, a[0]);
                a[1] = fmaf(v, wv.y, a[1]);
                a[2] = fmaf(v, wv.z, a[2]);
            }
        }
        __syncthreads();
    }
#pragma unroll
    for (int dy = 0; dy < 2; dy++)
#pragma unroll
        for (int dx = 0; dx < 2; dx++) {
            const int oy = oy0 + 2 * sy + dy, ox = ox0 + 2 * sx + dx;
#pragma unroll
            for (int j = 0; j < 3; j++)
                out[((n * 3 + j) * Hout + oy) * Wout + ox] = acc[dy * 2 + dx][j] + bias[j];
        }
}

// ---------------------------------------------------------------------------
// Fused 1x1 conv (Cin -> 64, optional channel-concat input) + vector quantize.
// One thread per pixel; f[64] in registers. Block 256.
// ---------------------------------------------------------------------------
__global__ __launch_bounds__(256) void conv1x1_quantize_kernel(
    const float* __restrict__ inA, const float* __restrict__ inB, int CA, int CB,
    const float* __restrict__ w, const float* __restrict__ b,
    const float* __restrict__ embed, const float* __restrict__ norms,
    float* __restrict__ qout, float* __restrict__ idout, float* __restrict__ acc,
    int HW) {
    const int tid = threadIdx.x;
    const int v = blockIdx.x * 256 + tid;
    const int n = v / HW, hw = v - n * HW;
    const int Cin = CA + CB;

    __shared__ float s_w[16][68];
    __shared__ float s_e[128][68];
    __shared__ float s_n[128];

    float f[64];
#pragma unroll
    for (int i = 0; i < 64; i++) f[i] = 0.f;

    // ---- 1x1 conv: f[co] = sum_ci in[ci] * w[co][ci] ----
    for (int ci0 = 0; ci0 < Cin; ci0 += 16) {
        for (int idx = tid; idx < 1024; idx += 256) {
            int c = idx & 15, co = idx >> 4;
            s_w[c][co] = w[co * Cin + ci0 + c];
        }
        __syncthreads();
#pragma unroll 4
        for (int c = 0; c < 16; c++) {
            const int ci = ci0 + c;
            float val;
            if (ci < CA)
                val = inA[(n * CA + ci) * HW + hw];
            else
                val = inB[(n * CB + (ci - CA)) * HW + hw];
            const float4* wr = (const float4*)s_w[c];
#pragma unroll
            for (int j = 0; j < 16; j++) {
                const float4 wv = wr[j];
                f[4 * j + 0] = fmaf(val, wv.x, f[4 * j + 0]);
                f[4 * j + 1] = fmaf(val, wv.y, f[4 * j + 1]);
                f[4 * j + 2] = fmaf(val, wv.z, f[4 * j + 2]);
                f[4 * j + 3] = fmaf(val, wv.w, f[4 * j + 3]);
            }
        }
        __syncthreads();
    }
    const float4* b4 = (const float4*)b;
#pragma unroll
    for (int j = 0; j < 16; j++) {
        const float4 bv = b4[j];
        f[4 * j + 0] += bv.x;
        f[4 * j + 1] += bv.y;
        f[4 * j + 2] += bv.z;
        f[4 * j + 3] += bv.w;
    }

    // ---- argmin_k ( ||e_k||^2 - 2 f.e_k ) ----
    float best = 3.4e38f;
    int bid = 0;
    for (int k0 = 0; k0 < 512; k0 += 128) {
        for (int idx = tid; idx < 8192; idx += 256) {
            int d = idx >> 7, k = idx & 127;
            s_e[k][d] = embed[d * 512 + k0 + k];
        }
        if (tid < 128) s_n[tid] = norms[k0 + tid];
        __syncthreads();
        for (int k = 0; k < 128; k++) {
            float d0 = 0.f, d1 = 0.f, d2 = 0.f, d3 = 0.f;
            const float4* er = (const float4*)s_e[k];
#pragma unroll
            for (int j = 0; j < 16; j++) {
                const float4 e = er[j];
                d0 = fmaf(f[4 * j + 0], e.x, d0);
                d1 = fmaf(f[4 * j + 1], e.y, d1);
                d2 = fmaf(f[4 * j + 2], e.z, d2);
                d3 = fmaf(f[4 * j + 3], e.w, d3);
            }
            const float sc = s_n[k] - 2.f * ((d0 + d1) + (d2 + d3));
            if (sc < best) { best = sc; bid = k0 + k; }
        }
        __syncthreads();
    }

    // ---- emit quantized vector, index, commitment-loss partial ----
    float lsum = 0.f;
#pragma unroll
    for (int d = 0; d < 64; d++) {
        const float q = __ldg(&embed[d * 512 + bid]);
        const float df = q - f[d];
        lsum = fmaf(df, df, lsum);
        qout[(n * 64 + d) * HW + hw] = q;
    }
    idout[v] = (float)bid;
#pragma unroll
    for (int o = 16; o > 0; o >>= 1) lsum += __shfl_down_sync(0xffffffffu, lsum, o);
    if ((tid & 31) == 0) atomicAdd(acc, lsum);
}

__global__ void finalize_loss_kernel(const float* __restrict__ acc, float* __restrict__ o) {
    o[0] = acc[0] * (1.f / 1048576.f) + acc[1] * (1.f / 4194304.f);
}

// ---------------------------------------------------------------------------
// host launcher
// ---------------------------------------------------------------------------
extern "C" void kernel_launch(void* const* d_in, const int* in_sizes, int n_in,
                              void* d_out, int out_size) {
    (void)in_sizes; (void)n_in; (void)out_size;
    const float* x       = (const float*)d_in[0];
    const float* wb1     = (const float*)d_in[1];
    const float* bb1     = (const float*)d_in[2];
    const float* wb2     = (const float*)d_in[3];
    const float* bb2     = (const float*)d_in[4];
    const float* wt1     = (const float*)d_in[5];
    const float* bt1     = (const float*)d_in[6];
    const float* wqt     = (const float*)d_in[7];
    const float* bqt     = (const float*)d_in[8];
    const float* embed_t = (const float*)d_in[9];
    const float* wdt     = (const float*)d_in[10];
    const float* bdt     = (const float*)d_in[11];
    const float* wqb     = (const float*)d_in[12];
    const float* bqb     = (const float*)d_in[13];
    const float* embed_b = (const float*)d_in[14];
    const float* wup     = (const float*)d_in[15];
    const float* bup     = (const float*)d_in[16];
    const float* wd1     = (const float*)d_in[17];
    const float* bd1     = (const float*)d_in[18];
    const float* wd2     = (const float*)d_in[19];
    const float* bd2     = (const float*)d_in[20];

    float* out    = (float*)d_out;
    float* o_xhat = out;                 // 16*3*256*256   = 3145728
    float* o_qt   = out + 3145728;       // 16*64*32*32    = 1048576
    float* o_qb   = out + 4194304;       // 16*64*64*64    = 4194304
    float* o_loss = out + 8388608;       // 1
    float* o_idt  = out + 8388609;       // 16*32*32       = 16384
    float* o_idb  = out + 8404993;       // 16*64*64       = 65536

    float *encb1, *encb, *enct, *dect, *upt, *h, *normt, *normb, *acc;
    cudaGetSymbolAddress((void**)&encb1, g_encb1);
    cudaGetSymbolAddress((void**)&encb,  g_encb);
    cudaGetSymbolAddress((void**)&enct,  g_enct);
    cudaGetSymbolAddress((void**)&dect,  g_dect);
    cudaGetSymbolAddress((void**)&upt,   g_upt);
    cudaGetSymbolAddress((void**)&h,     g_h);
    cudaGetSymbolAddress((void**)&normt, g_normt);
    cudaGetSymbolAddress((void**)&normb, g_normb);
    cudaGetSymbolAddress((void**)&acc,   g_acc);

    init_kernel<<<1, 512>>>(embed_t, embed_b, normt, normb, acc);

    // ---- encoder ----
    conv4x4s2_kernel<true><<<dim3(8, 8, 16 * 4), 256>>>(x, wb1, bb1, encb1, 16, 3, 128, 256, 256);
    conv4x4s2_kernel<true><<<dim3(4, 4, 16 * 4), 256>>>(encb1, wb2, bb2, encb, 16, 128, 128, 128, 128);
    conv4x4s2_kernel<true><<<dim3(2, 2, 16 * 4), 256>>>(encb, wt1, bt1, enct, 16, 128, 128, 64, 64);

    // ---- top quantize ----
    conv1x1_quantize_kernel<<<16384 / 256, 256>>>(enct, enct, 128, 0, wqt, bqt,
                                                  embed_t, normt, o_qt, o_idt, acc + 0, 1024);

    // ---- decoder_top, bottom quantize ----
    convT4x4_kernel<false><<<dim3(4, 4, 16 * 2), 256>>>(o_qt, o_qt, 64, wdt, bdt, dect, 16, 64, 64, 32, 32);
    conv1x1_quantize_kernel<<<65536 / 256, 256>>>(dect, encb, 64, 128, wqb, bqb,
                                                  embed_b, normb, o_qb, o_idb, acc + 1, 4096);

    // ---- decode ----
    convT4x4_kernel<false><<<dim3(4, 4, 16 * 2), 256>>>(o_qt, o_qt, 64, wup, bup, upt, 16, 64, 64, 32, 32);
    convT4x4_kernel<true><<<dim3(8, 8, 16 * 2), 256>>>(upt, o_qb, 64, wd1, bd1, h, 16, 128, 64, 64, 64);
    convT4x4_small_kernel<<<dim3(8, 8, 16), 256>>>(h, wd2, bd2, o_xhat, 16, 64, 128, 128);

    finalize_loss_kernel<<<1, 1>>>(acc, o_loss);
}

// round 3
// speedup vs baseline: 1.3171x; 1.0199x over previous
#include <cuda_runtime.h>
#include <cuda_bf16.h>

typedef unsigned long long u64t;

__device__ __forceinline__ void ffma2(u64t& d, u64t a, u64t b) {
    asm("fma.rn.f32x2 %0, %1, %2, %0;" : "+l"(d) : "l"(a), "l"(b));
}
__device__ __forceinline__ u64t packdup(float v) {
    u64t r;
    asm("mov.b64 %0, {%1, %1};" : "=l"(r) : "r"(__float_as_uint(v)));
    return r;
}
__device__ __forceinline__ u64t pack2(float a, float b) {
    u64t r;
    asm("mov.b64 %0, {%1, %2};" : "=l"(r) : "r"(__float_as_uint(a)), "r"(__float_as_uint(b)));
    return r;
}
__device__ __forceinline__ float2 unpk(u64t p) {
    unsigned lo, hi;
    asm("mov.b64 {%0, %1}, %2;" : "=r"(lo), "=r"(hi) : "l"(p));
    return make_float2(__uint_as_float(lo), __uint_as_float(hi));
}

__device__ float g_encb1[16 * 128 * 128 * 128];
__device__ float g_encb [16 * 128 * 64 * 64];
__device__ float g_enct [16 * 128 * 32 * 32];
__device__ float g_dect [16 * 64 * 64 * 64];
__device__ float g_upt  [16 * 64 * 64 * 64];
__device__ float g_h    [16 * 64 * 128 * 128];
__device__ float g_normt[512];
__device__ float g_normb[512];
__device__ float g_acc[2];

__global__ void init_kernel(const float* __restrict__ et, const float* __restrict__ eb,
                            float* __restrict__ nt, float* __restrict__ nb,
                            float* __restrict__ acc) {
    int k = threadIdx.x; // 512 threads
    float st = 0.f, sb = 0.f;
#pragma unroll
    for (int d = 0; d < 64; d++) {
        float a = et[d * 512 + k]; st = fmaf(a, a, st);
        float b = eb[d * 512 + k]; sb = fmaf(b, b, sb);
    }
    nt[k] = st;
    nb[k] = sb;
    if (k < 2) acc[k] = 0.f;
}

// ---------------------------------------------------------------------------
// 4x4 stride-2 pad-1 conv (+ optional relu), f32x2 packed math.
// ---------------------------------------------------------------------------
#define CCHNK 4
template <bool RELU>
__global__ __launch_bounds__(256, 3) void conv4x4s2_kernel(
    const float* __restrict__ in, const float* __restrict__ w,
    const float* __restrict__ bias, float* __restrict__ out,
    int N, int Cin, int Cout, int Hin, int Win) {
    const int Hout = Hin >> 1, Wout = Win >> 1;
    const int tid = threadIdx.x;
    const int lane4 = tid & 3;
    const int sp = tid >> 2;
    const int sx = sp & 7, sy = sp >> 3;
    const int ox0 = blockIdx.x << 4, oy0 = blockIdx.y << 4;
    const int cog = Cout >> 5;
    const int n = blockIdx.z / cog;
    const int co0 = (blockIdx.z % cog) << 5;

    __shared__ float s_in[CCHNK][34][34];
    __shared__ float s_w[CCHNK][16][36];

    u64t acc2[4][4];
#pragma unroll
    for (int p = 0; p < 4; p++)
#pragma unroll
        for (int j = 0; j < 4; j++) acc2[p][j] = 0ull;

    const int iyb = 2 * oy0 - 1, ixb = 2 * ox0 - 1;
    const int by = 4 * sy, bx = 4 * sx;

    for (int ci0 = 0; ci0 < Cin; ci0 += CCHNK) {
        const int cc = min(CCHNK, Cin - ci0);
        for (int idx = tid; idx < cc * 1156; idx += 256) {
            int c = idx / 1156, r = idx - c * 1156;
            int yy = r / 34, xx = r - yy * 34;
            int iy = iyb + yy, ix = ixb + xx;
            float v = 0.f;
            if ((unsigned)iy < (unsigned)Hin && (unsigned)ix < (unsigned)Win)
                v = in[((n * Cin + ci0 + c) * Hin + iy) * Win + ix];
            s_in[c][yy][xx] = v;
        }
        const int cseg = cc * 16;
        for (int idx = tid; idx < cc * 512; idx += 256) {
            int co = idx / cseg;
            int r = idx - co * cseg;
            int c = r >> 4, kk = r & 15;
            s_w[c][kk][co] = w[(co0 + co) * Cin * 16 + ci0 * 16 + r];
        }
        __syncthreads();
        for (int c = 0; c < cc; c++) {
#pragma unroll
            for (int kk = 0; kk < 16; kk++) {
                const int ky = kk >> 2, kx = kk & 3;
                const u64t v00 = packdup(s_in[c][by + ky][bx + kx]);
                const u64t v01 = packdup(s_in[c][by + ky][bx + kx + 2]);
                const u64t v10 = packdup(s_in[c][by + ky + 2][bx + kx]);
                const u64t v11 = packdup(s_in[c][by + ky + 2][bx + kx + 2]);
                const float* wp = &s_w[c][kk][lane4 * 8];
                const ulonglong2 wA = *(const ulonglong2*)(wp);
                const ulonglong2 wB = *(const ulonglong2*)(wp + 4);
                ffma2(acc2[0][0], v00, wA.x); ffma2(acc2[0][1], v00, wA.y);
                ffma2(acc2[0][2], v00, wB.x); ffma2(acc2[0][3], v00, wB.y);
                ffma2(acc2[1][0], v01, wA.x); ffma2(acc2[1][1], v01, wA.y);
                ffma2(acc2[1][2], v01, wB.x); ffma2(acc2[1][3], v01, wB.y);
                ffma2(acc2[2][0], v10, wA.x); ffma2(acc2[2][1], v10, wA.y);
                ffma2(acc2[2][2], v10, wB.x); ffma2(acc2[2][3], v10, wB.y);
                ffma2(acc2[3][0], v11, wA.x); ffma2(acc2[3][1], v11, wA.y);
                ffma2(acc2[3][2], v11, wB.x); ffma2(acc2[3][3], v11, wB.y);
            }
        }
        __syncthreads();
    }
#pragma unroll
    for (int dy = 0; dy < 2; dy++)
#pragma unroll
        for (int dx = 0; dx < 2; dx++) {
            const int oy = oy0 + 2 * sy + dy, ox = ox0 + 2 * sx + dx;
#pragma unroll
            for (int j = 0; j < 4; j++) {
                const int co = co0 + lane4 * 8 + 2 * j;
                const float2 pv = unpk(acc2[dy * 2 + dx][j]);
                float r0 = pv.x + bias[co];
                float r1 = pv.y + bias[co + 1];
                if (RELU) { r0 = fmaxf(r0, 0.f); r1 = fmaxf(r1, 0.f); }
                out[((n * Cout + co) * Hout + oy) * Wout + ox] = r0;
                out[((n * Cout + co + 1) * Hout + oy) * Wout + ox] = r1;
            }
        }
}

// ---------------------------------------------------------------------------
// convT, f32x2 packed
// ---------------------------------------------------------------------------
#define TCHNK 8
template <bool RELU>
__global__ __launch_bounds__(256, 3) void convT4x4_kernel(
    const float* __restrict__ inA, const float* __restrict__ inB, int CA,
    const float* __restrict__ w, const float* __restrict__ bias,
    float* __restrict__ out, int N, int Cin, int Cout, int Hin, int Win) {
    const int Hout = Hin << 1, Wout = Win << 1;
    const int tid = threadIdx.x;
    const int lane4 = tid & 3;
    const int sp = tid >> 2;
    const int sx = sp & 7, sy = sp >> 3;
    const int ox0 = blockIdx.x << 4, oy0 = blockIdx.y << 4;
    const int cog = Cout >> 5;
    const int n = blockIdx.z / cog;
    const int co0 = (blockIdx.z % cog) << 5;
    const int CB = Cin - CA;

    __shared__ float s_in[TCHNK][10][10];
    __shared__ float s_w[TCHNK][16][36];

    u64t acc2[4][4];
#pragma unroll
    for (int p = 0; p < 4; p++)
#pragma unroll
        for (int j = 0; j < 4; j++) acc2[p][j] = 0ull;

    const int iy0 = (oy0 >> 1) - 1, ix0 = (ox0 >> 1) - 1;

    for (int ci0 = 0; ci0 < Cin; ci0 += TCHNK) {
        const int cc = min(TCHNK, Cin - ci0);
        for (int idx = tid; idx < cc * 100; idx += 256) {
            int c = idx / 100, r = idx - c * 100;
            int yy = r / 10, xx = r - yy * 10;
            int iy = iy0 + yy, ix = ix0 + xx;
            int ci = ci0 + c;
            float v = 0.f;
            if ((unsigned)iy < (unsigned)Hin && (unsigned)ix < (unsigned)Win) {
                if (ci < CA)
                    v = inA[((n * CA + ci) * Hin + iy) * Win + ix];
                else
                    v = inB[((n * CB + (ci - CA)) * Hin + iy) * Win + ix];
            }
            s_in[c][yy][xx] = v;
        }
        for (int idx = tid; idx < cc * 512; idx += 256) {
            int c = idx >> 9, r = idx & 511;
            int co = r >> 4, kk = r & 15;
            s_w[c][kk][co] = w[(ci0 + c) * Cout * 16 + co0 * 16 + r];
        }
        __syncthreads();
        for (int c = 0; c < cc; c++) {
            u64t vin[3][3];
#pragma unroll
            for (int i = 0; i < 3; i++)
#pragma unroll
                for (int j2 = 0; j2 < 3; j2++) vin[i][j2] = packdup(s_in[c][sy + i][sx + j2]);
#pragma unroll
            for (int kk = 0; kk < 16; kk++) {
                const int ky = kk >> 2, kx = kk & 3;
                const int dy = (ky & 1) ? 0 : 1;
                const int ry = (ky & 1) ? (1 - ((ky - 1) >> 1)) : (2 - (ky >> 1));
                const int dx = (kx & 1) ? 0 : 1;
                const int rx = (kx & 1) ? (1 - ((kx - 1) >> 1)) : (2 - (kx >> 1));
                const u64t v = vin[ry][rx];
                const float* wp = &s_w[c][kk][lane4 * 8];
                const ulonglong2 wA = *(const ulonglong2*)(wp);
                const ulonglong2 wB = *(const ulonglong2*)(wp + 4);
                u64t* a = acc2[dy * 2 + dx];
                ffma2(a[0], v, wA.x);
                ffma2(a[1], v, wA.y);
                ffma2(a[2], v, wB.x);
                ffma2(a[3], v, wB.y);
            }
        }
        __syncthreads();
    }
#pragma unroll
    for (int dy = 0; dy < 2; dy++)
#pragma unroll
        for (int dx = 0; dx < 2; dx++) {
            const int oy = oy0 + 2 * sy + dy, ox = ox0 + 2 * sx + dx;
#pragma unroll
            for (int j = 0; j < 4; j++) {
                const int co = co0 + lane4 * 8 + 2 * j;
                const float2 pv = unpk(acc2[dy * 2 + dx][j]);
                float r0 = pv.x + bias[co];
                float r1 = pv.y + bias[co + 1];
                if (RELU) { r0 = fmaxf(r0, 0.f); r1 = fmaxf(r1, 0.f); }
                out[((n * Cout + co) * Hout + oy) * Wout + ox] = r0;
                out[((n * Cout + co + 1) * Hout + oy) * Wout + ox] = r1;
            }
        }
}

// ---------------------------------------------------------------------------
// ConvT small (Cout=3)
// ---------------------------------------------------------------------------
__global__ __launch_bounds__(256) void convT4x4_small_kernel(
    const float* __restrict__ in, const float* __restrict__ w,
    const float* __restrict__ bias, float* __restrict__ out,
    int N, int Cin, int Hin, int Win) {
    const int Hout = Hin << 1, Wout = Win << 1;
    const int tid = threadIdx.x;
    const int sx = tid & 15, sy = tid >> 4;
    const int ox0 = blockIdx.x << 5, oy0 = blockIdx.y << 5;
    const int n = blockIdx.z;

    __shared__ float s_in[TCHNK][18][18];
    __shared__ float s_w[TCHNK][16][4];

    u64t acc01[4];
    float acc2s[4];
#pragma unroll
    for (int p = 0; p < 4; p++) { acc01[p] = 0ull; acc2s[p] = 0.f; }

    const int iy0 = (oy0 >> 1) - 1, ix0 = (ox0 >> 1) - 1;

    for (int ci0 = 0; ci0 < Cin; ci0 += TCHNK) {
        const int cc = min(TCHNK, Cin - ci0);
        for (int idx = tid; idx < cc * 324; idx += 256) {
            int c = idx / 324, r = idx - c * 324;
            int yy = r / 18, xx = r - yy * 18;
            int iy = iy0 + yy, ix = ix0 + xx;
            float v = 0.f;
            if ((unsigned)iy < (unsigned)Hin && (unsigned)ix < (unsigned)Win)
                v = in[((n * Cin + ci0 + c) * Hin + iy) * Win + ix];
            s_in[c][yy][xx] = v;
        }
        for (int idx = tid; idx < cc * 48; idx += 256) {
            int c = idx / 48, r = idx - c * 48;
            int co = r >> 4, kk = r & 15;
            s_w[c][kk][co] = w[(ci0 + c) * 3 * 16 + r];
        }
        __syncthreads();
        for (int c = 0; c < cc; c++) {
            float vin[3][3];
#pragma unroll
            for (int i = 0; i < 3; i++)
#pragma unroll
                for (int j2 = 0; j2 < 3; j2++) vin[i][j2] = s_in[c][sy + i][sx + j2];
#pragma unroll
            for (int kk = 0; kk < 16; kk++) {
                const int ky = kk >> 2, kx = kk & 3;
                const int dy = (ky & 1) ? 0 : 1;
                const int ry = (ky & 1) ? (1 - ((ky - 1) >> 1)) : (2 - (ky >> 1));
                const int dx = (kx & 1) ? 0 : 1;
                const int rx = (kx & 1) ? (1 - ((kx - 1) >> 1)) : (2 - (kx >> 1));
                const float vs = vin[ry][rx];
                const u64t v = packdup(vs);
                const u64t w01 = *(const u64t*)&s_w[c][kk][0];
                const int p = dy * 2 + dx;
                ffma2(acc01[p], v, w01);
                acc2s[p] = fmaf(vs, s_w[c][kk][2], acc2s[p]);
            }
        }
        __syncthreads();
    }
#pragma unroll
    for (int dy = 0; dy < 2; dy++)
#pragma unroll
        for (int dx = 0; dx < 2; dx++) {
            const int oy = oy0 + 2 * sy + dy, ox = ox0 + 2 * sx + dx;
            const float2 pv = unpk(acc01[dy * 2 + dx]);
            out[((n * 3 + 0) * Hout + oy) * Wout + ox] = pv.x + bias[0];
            out[((n * 3 + 1) * Hout + oy) * Wout + ox] = pv.y + bias[1];
            out[((n * 3 + 2) * Hout + oy) * Wout + ox] = acc2s[dy * 2 + dx] + bias[2];
        }
}

// ---------------------------------------------------------------------------
// Fused 1x1 conv + VQ, f32x2 packed
// ---------------------------------------------------------------------------
__global__ __launch_bounds__(256) void conv1x1_quantize_kernel(
    const float* __restrict__ inA, const float* __restrict__ inB, int CA, int CB,
    const float* __restrict__ w, const float* __restrict__ b,
    const float* __restrict__ embed, const float* __restrict__ norms,
    float* __restrict__ qout, float* __restrict__ idout, float* __restrict__ acc,
    int HW) {
    const int tid = threadIdx.x;
    const int v = blockIdx.x * 256 + tid;
    const int n = v / HW, hw = v - n * HW;
    const int Cin = CA + CB;

    __shared__ float s_w[16][68];
    __shared__ float s_e[128][68];
    __shared__ float s_n[128];

    u64t f2[32];
#pragma unroll
    for (int i = 0; i < 32; i++) f2[i] = 0ull;

    for (int ci0 = 0; ci0 < Cin; ci0 += 16) {
        for (int idx = tid; idx < 1024; idx += 256) {
            int c = idx & 15, co = idx >> 4;
            s_w[c][co] = w[co * Cin + ci0 + c];
        }
        __syncthreads();
#pragma unroll 4
        for (int c = 0; c < 16; c++) {
            const int ci = ci0 + c;
            float val;
            if (ci < CA)
                val = inA[(n * CA + ci) * HW + hw];
            else
                val = inB[(n * CB + (ci - CA)) * HW + hw];
            const u64t vp = packdup(val);
            const ulonglong2* wr = (const ulonglong2*)s_w[c];
#pragma unroll
            for (int j = 0; j < 16; j++) {
                const ulonglong2 wv = wr[j];
                ffma2(f2[2 * j + 0], vp, wv.x);
                ffma2(f2[2 * j + 1], vp, wv.y);
            }
        }
        __syncthreads();
    }
    // bias
    float f[64];
#pragma unroll
    for (int i = 0; i < 32; i++) {
        const float2 pv = unpk(f2[i]);
        f[2 * i] = pv.x + b[2 * i];
        f[2 * i + 1] = pv.y + b[2 * i + 1];
        f2[i] = pack2(f[2 * i], f[2 * i + 1]);
    }

    float best = 3.4e38f;
    int bid = 0;
    for (int k0 = 0; k0 < 512; k0 += 128) {
        for (int idx = tid; idx < 8192; idx += 256) {
            int d = idx >> 7, k = idx & 127;
            s_e[k][d] = embed[d * 512 + k0 + k];
        }
        if (tid < 128) s_n[tid] = norms[k0 + tid];
        __syncthreads();
        for (int k = 0; k < 128; k++) {
            u64t d0 = 0ull, d1 = 0ull;
            const ulonglong2* er = (const ulonglong2*)s_e[k];
#pragma unroll
            for (int j = 0; j < 16; j++) {
                const ulonglong2 e = er[j];
                ffma2(d0, f2[2 * j + 0], e.x);
                ffma2(d1, f2[2 * j + 1], e.y);
            }
            const float2 a0 = unpk(d0), a1 = unpk(d1);
            const float sc = s_n[k] - 2.f * ((a0.x + a0.y) + (a1.x + a1.y));
            if (sc < best) { best = sc; bid = k0 + k; }
        }
        __syncthreads();
    }

    float lsum = 0.f;
#pragma unroll
    for (int d = 0; d < 64; d++) {
        const float q = __ldg(&embed[d * 512 + bid]);
        const float df = q - f[d];
        lsum = fmaf(df, df, lsum);
        qout[(n * 64 + d) * HW + hw] = q;
    }
    idout[v] = (float)bid;
#pragma unroll
    for (int o = 16; o > 0; o >>= 1) lsum += __shfl_down_sync(0xffffffffu, lsum, o);
    if ((tid & 31) == 0) atomicAdd(acc, lsum);
}

__global__ void finalize_loss_kernel(const float* __restrict__ acc, float* __restrict__ o) {
    o[0] = acc[0] * (1.f / 1048576.f) + acc[1] * (1.f / 4194304.f);
}

extern "C" void kernel_launch(void* const* d_in, const int* in_sizes, int n_in,
                              void* d_out, int out_size) {
    (void)in_sizes; (void)n_in; (void)out_size;
    const float* x       = (const float*)d_in[0];
    const float* wb1     = (const float*)d_in[1];
    const float* bb1     = (const float*)d_in[2];
    const float* wb2     = (const float*)d_in[3];
    const float* bb2     = (const float*)d_in[4];
    const float* wt1     = (const float*)d_in[5];
    const float* bt1     = (const float*)d_in[6];
    const float* wqt     = (const float*)d_in[7];
    const float* bqt     = (const float*)d_in[8];
    const float* embed_t = (const float*)d_in[9];
    const float* wdt     = (const float*)d_in[10];
    const float* bdt     = (const float*)d_in[11];
    const float* wqb     = (const float*)d_in[12];
    const float* bqb     = (const float*)d_in[13];
    const float* embed_b = (const float*)d_in[14];
    const float* wup     = (const float*)d_in[15];
    const float* bup     = (const float*)d_in[16];
    const float* wd1     = (const float*)d_in[17];
    const float* bd1     = (const float*)d_in[18];
    const float* wd2     = (const float*)d_in[19];
    const float* bd2     = (const float*)d_in[20];

    float* out    = (float*)d_out;
    float* o_xhat = out;
    float* o_qt   = out + 3145728;
    float* o_qb   = out + 4194304;
    float* o_loss = out + 8388608;
    float* o_idt  = out + 8388609;
    float* o_idb  = out + 8404993;

    float *encb1, *encb, *enct, *dect, *upt, *h, *normt, *normb, *acc;
    cudaGetSymbolAddress((void**)&encb1, g_encb1);
    cudaGetSymbolAddress((void**)&encb,  g_encb);
    cudaGetSymbolAddress((void**)&enct,  g_enct);
    cudaGetSymbolAddress((void**)&dect,  g_dect);
    cudaGetSymbolAddress((void**)&upt,   g_upt);
    cudaGetSymbolAddress((void**)&h,     g_h);
    cudaGetSymbolAddress((void**)&normt, g_normt);
    cudaGetSymbolAddress((void**)&normb, g_normb);
    cudaGetSymbolAddress((void**)&acc,   g_acc);

    init_kernel<<<1, 512>>>(embed_t, embed_b, normt, normb, acc);

    conv4x4s2_kernel<true><<<dim3(8, 8, 16 * 4), 256>>>(x, wb1, bb1, encb1, 16, 3, 128, 256, 256);
    conv4x4s2_kernel<true><<<dim3(4, 4, 16 * 4), 256>>>(encb1, wb2, bb2, encb, 16, 128, 128, 128, 128);
    conv4x4s2_kernel<true><<<dim3(2, 2, 16 * 4), 256>>>(encb, wt1, bt1, enct, 16, 128, 128, 64, 64);

    conv1x1_quantize_kernel<<<16384 / 256, 256>>>(enct, enct, 128, 0, wqt, bqt,
                                                  embed_t, normt, o_qt, o_idt, acc + 0, 1024);

    convT4x4_kernel<false><<<dim3(4, 4, 16 * 2), 256>>>(o_qt, o_qt, 64, wdt, bdt, dect, 16, 64, 64, 32, 32);
    conv1x1_quantize_kernel<<<65536 / 256, 256>>>(dect, encb, 64, 128, wqb, bqb,
                                                  embed_b, normb, o_qb, o_idb, acc + 1, 4096);

    convT4x4_kernel<false><<<dim3(4, 4, 16 * 2), 256>>>(o_qt, o_qt, 64, wup, bup, upt, 16, 64, 64, 32, 32);
    convT4x4_kernel<true><<<dim3(8, 8, 16 * 2), 256>>>(upt, o_qb, 64, wd1, bd1, h, 16, 128, 64, 64, 64);
    convT4x4_small_kernel<<<dim3(8, 8, 16), 256>>>(h, wd2, bd2, o_xhat, 16, 64, 128, 128);

    finalize_loss_kernel<<<1, 1>>>(acc, o_loss);
}

// round 4
// speedup vs baseline: 1.6015x; 1.2159x over previous
#include <cuda_runtime.h>
#include <cuda_bf16.h>

typedef unsigned long long u64t;

__device__ __forceinline__ void ffma2(u64t& d, u64t a, u64t b) {
    asm("fma.rn.f32x2 %0, %1, %2, %0;" : "+l"(d) : "l"(a), "l"(b));
}
__device__ __forceinline__ u64t packdup(float v) {
    u64t r;
    asm("mov.b64 %0, {%1, %1};" : "=l"(r) : "r"(__float_as_uint(v)));
    return r;
}
__device__ __forceinline__ u64t pack2(float a, float b) {
    u64t r;
    asm("mov.b64 %0, {%1, %2};" : "=l"(r) : "r"(__float_as_uint(a)), "r"(__float_as_uint(b)));
    return r;
}
__device__ __forceinline__ float2 unpk(u64t p) {
    unsigned lo, hi;
    asm("mov.b64 {%0, %1}, %2;" : "=r"(lo), "=r"(hi) : "l"(p));
    return make_float2(__uint_as_float(lo), __uint_as_float(hi));
}
__device__ __forceinline__ void cp_async4(void* smem, const void* gmem) {
    unsigned s = (unsigned)__cvta_generic_to_shared(smem);
    asm volatile("cp.async.ca.shared.global [%0], [%1], 4;" :: "r"(s), "l"(gmem));
}
__device__ __forceinline__ void cp_commit() {
    asm volatile("cp.async.commit_group;" ::: "memory");
}
template <int N>
__device__ __forceinline__ void cp_wait() {
    asm volatile("cp.async.wait_group %0;" :: "n"(N) : "memory");
}

__device__ float g_encb1[16 * 128 * 128 * 128];
__device__ float g_encb [16 * 128 * 64 * 64];
__device__ float g_enct [16 * 128 * 32 * 32];
__device__ float g_dect [16 * 64 * 64 * 64];
__device__ float g_upt  [16 * 64 * 64 * 64];
__device__ float g_h    [16 * 64 * 128 * 128];
__device__ float g_normt[512];
__device__ float g_normb[512];
__device__ float g_acc[2];

__global__ void init_kernel(const float* __restrict__ et, const float* __restrict__ eb,
                            float* __restrict__ nt, float* __restrict__ nb,
                            float* __restrict__ acc) {
    int k = threadIdx.x; // 512 threads
    float st = 0.f, sb = 0.f;
#pragma unroll
    for (int d = 0; d < 64; d++) {
        float a = et[d * 512 + k]; st = fmaf(a, a, st);
        float b = eb[d * 512 + k]; sb = fmaf(b, b, sb);
    }
    nt[k] = st;
    nb[k] = sb;
    if (k < 2) acc[k] = 0.f;
}

// ---------------------------------------------------------------------------
// 4x4 stride-2 pad-1 conv (+relu), f32x2 math, cp.async double-buffered.
// ---------------------------------------------------------------------------
#define CCHNK 4
template <bool RELU>
__global__ __launch_bounds__(256, 3) void conv4x4s2_kernel(
    const float* __restrict__ in, const float* __restrict__ w,
    const float* __restrict__ bias, float* __restrict__ out,
    int N, int Cin, int Cout, int Hin, int Win) {
    const int Hout = Hin >> 1, Wout = Win >> 1;
    const int tid = threadIdx.x;
    const int lane4 = tid & 3;
    const int sp = tid >> 2;
    const int sx = sp & 7, sy = sp >> 3;
    const int ox0 = blockIdx.x << 4, oy0 = blockIdx.y << 4;
    const int cog = Cout >> 5;
    const int n = blockIdx.z / cog;
    const int co0 = (blockIdx.z % cog) << 5;

    __shared__ float s_in[2][CCHNK][34][34];
    __shared__ float s_w[2][CCHNK][16][36];

    u64t acc2[4][4];
#pragma unroll
    for (int p = 0; p < 4; p++)
#pragma unroll
        for (int j = 0; j < 4; j++) acc2[p][j] = 0ull;

    const int iyb = 2 * oy0 - 1, ixb = 2 * ox0 - 1;
    const int by = 4 * sy, bx = 4 * sx;

    // zero both input buffers once (OOB fringe is iteration-invariant)
    for (int idx = tid; idx < 2 * CCHNK * 1156; idx += 256)
        ((float*)s_in)[idx] = 0.f;
    __syncthreads();

    auto load_chunk = [&](int ci0, int buf) {
        const int cc = min(CCHNK, Cin - ci0);
        for (int idx = tid; idx < cc * 1156; idx += 256) {
            int c = idx / 1156, r = idx - c * 1156;
            int yy = r / 34, xx = r - yy * 34;
            int iy = iyb + yy, ix = ixb + xx;
            if ((unsigned)iy < (unsigned)Hin && (unsigned)ix < (unsigned)Win)
                cp_async4(&s_in[buf][c][yy][xx],
                          &in[((n * Cin + ci0 + c) * Hin + iy) * Win + ix]);
        }
        const int cseg = cc * 16;
        for (int idx = tid; idx < cc * 512; idx += 256) {
            int co = idx / cseg;
            int r = idx - co * cseg;
            int c = r >> 4, kk = r & 15;
            cp_async4(&s_w[buf][c][kk][co], &w[(co0 + co) * Cin * 16 + ci0 * 16 + r]);
        }
        cp_commit();
    };

    const int nch = (Cin + CCHNK - 1) / CCHNK;
    load_chunk(0, 0);
    for (int it = 0; it < nch; it++) {
        const int buf = it & 1;
        if (it + 1 < nch) { load_chunk((it + 1) * CCHNK, buf ^ 1); cp_wait<1>(); }
        else cp_wait<0>();
        __syncthreads();
        const int cc = min(CCHNK, Cin - it * CCHNK);
        for (int c = 0; c < cc; c++) {
#pragma unroll
            for (int kk = 0; kk < 16; kk++) {
                const int ky = kk >> 2, kx = kk & 3;
                const u64t v00 = packdup(s_in[buf][c][by + ky][bx + kx]);
                const u64t v01 = packdup(s_in[buf][c][by + ky][bx + kx + 2]);
                const u64t v10 = packdup(s_in[buf][c][by + ky + 2][bx + kx]);
                const u64t v11 = packdup(s_in[buf][c][by + ky + 2][bx + kx + 2]);
                const float* wp = &s_w[buf][c][kk][lane4 * 8];
                const ulonglong2 wA = *(const ulonglong2*)(wp);
                const ulonglong2 wB = *(const ulonglong2*)(wp + 4);
                ffma2(acc2[0][0], v00, wA.x); ffma2(acc2[0][1], v00, wA.y);
                ffma2(acc2[0][2], v00, wB.x); ffma2(acc2[0][3], v00, wB.y);
                ffma2(acc2[1][0], v01, wA.x); ffma2(acc2[1][1], v01, wA.y);
                ffma2(acc2[1][2], v01, wB.x); ffma2(acc2[1][3], v01, wB.y);
                ffma2(acc2[2][0], v10, wA.x); ffma2(acc2[2][1], v10, wA.y);
                ffma2(acc2[2][2], v10, wB.x); ffma2(acc2[2][3], v10, wB.y);
                ffma2(acc2[3][0], v11, wA.x); ffma2(acc2[3][1], v11, wA.y);
                ffma2(acc2[3][2], v11, wB.x); ffma2(acc2[3][3], v11, wB.y);
            }
        }
        __syncthreads();
    }
#pragma unroll
    for (int dy = 0; dy < 2; dy++)
#pragma unroll
        for (int dx = 0; dx < 2; dx++) {
            const int oy = oy0 + 2 * sy + dy, ox = ox0 + 2 * sx + dx;
#pragma unroll
            for (int j = 0; j < 4; j++) {
                const int co = co0 + lane4 * 8 + 2 * j;
                const float2 pv = unpk(acc2[dy * 2 + dx][j]);
                float r0 = pv.x + bias[co];
                float r1 = pv.y + bias[co + 1];
                if (RELU) { r0 = fmaxf(r0, 0.f); r1 = fmaxf(r1, 0.f); }
                out[((n * Cout + co) * Hout + oy) * Wout + ox] = r0;
                out[((n * Cout + co + 1) * Hout + oy) * Wout + ox] = r1;
            }
        }
}

// ---------------------------------------------------------------------------
// convT, f32x2, cp.async double-buffered
// ---------------------------------------------------------------------------
#define TCHNK 8
template <bool RELU>
__global__ __launch_bounds__(256, 3) void convT4x4_kernel(
    const float* __restrict__ inA, const float* __restrict__ inB, int CA,
    const float* __restrict__ w, const float* __restrict__ bias,
    float* __restrict__ out, int N, int Cin, int Cout, int Hin, int Win) {
    const int Hout = Hin << 1, Wout = Win << 1;
    const int tid = threadIdx.x;
    const int lane4 = tid & 3;
    const int sp = tid >> 2;
    const int sx = sp & 7, sy = sp >> 3;
    const int ox0 = blockIdx.x << 4, oy0 = blockIdx.y << 4;
    const int cog = Cout >> 5;
    const int n = blockIdx.z / cog;
    const int co0 = (blockIdx.z % cog) << 5;
    const int CB = Cin - CA;

    __shared__ float s_in[2][TCHNK][10][10];
    __shared__ float s_w[2][TCHNK][16][36];

    u64t acc2[4][4];
#pragma unroll
    for (int p = 0; p < 4; p++)
#pragma unroll
        for (int j = 0; j < 4; j++) acc2[p][j] = 0ull;

    const int iy0 = (oy0 >> 1) - 1, ix0 = (ox0 >> 1) - 1;

    for (int idx = tid; idx < 2 * TCHNK * 100; idx += 256)
        ((float*)s_in)[idx] = 0.f;
    __syncthreads();

    auto load_chunk = [&](int ci0, int buf) {
        const int cc = min(TCHNK, Cin - ci0);
        for (int idx = tid; idx < cc * 100; idx += 256) {
            int c = idx / 100, r = idx - c * 100;
            int yy = r / 10, xx = r - yy * 10;
            int iy = iy0 + yy, ix = ix0 + xx;
            int ci = ci0 + c;
            if ((unsigned)iy < (unsigned)Hin && (unsigned)ix < (unsigned)Win) {
                const float* src = (ci < CA)
                    ? &inA[((n * CA + ci) * Hin + iy) * Win + ix]
                    : &inB[((n * CB + (ci - CA)) * Hin + iy) * Win + ix];
                cp_async4(&s_in[buf][c][yy][xx], src);
            }
        }
        for (int idx = tid; idx < cc * 512; idx += 256) {
            int c = idx >> 9, r = idx & 511;
            int co = r >> 4, kk = r & 15;
            cp_async4(&s_w[buf][c][kk][co], &w[(ci0 + c) * Cout * 16 + co0 * 16 + r]);
        }
        cp_commit();
    };

    const int nch = (Cin + TCHNK - 1) / TCHNK;
    load_chunk(0, 0);
    for (int it = 0; it < nch; it++) {
        const int buf = it & 1;
        if (it + 1 < nch) { load_chunk((it + 1) * TCHNK, buf ^ 1); cp_wait<1>(); }
        else cp_wait<0>();
        __syncthreads();
        const int cc = min(TCHNK, Cin - it * TCHNK);
        for (int c = 0; c < cc; c++) {
            u64t vin[3][3];
#pragma unroll
            for (int i = 0; i < 3; i++)
#pragma unroll
                for (int j2 = 0; j2 < 3; j2++) vin[i][j2] = packdup(s_in[buf][c][sy + i][sx + j2]);
#pragma unroll
            for (int kk = 0; kk < 16; kk++) {
                const int ky = kk >> 2, kx = kk & 3;
                const int dy = (ky & 1) ? 0 : 1;
                const int ry = (ky & 1) ? (1 - ((ky - 1) >> 1)) : (2 - (ky >> 1));
                const int dx = (kx & 1) ? 0 : 1;
                const int rx = (kx & 1) ? (1 - ((kx - 1) >> 1)) : (2 - (kx >> 1));
                const u64t v = vin[ry][rx];
                const float* wp = &s_w[buf][c][kk][lane4 * 8];
                const ulonglong2 wA = *(const ulonglong2*)(wp);
                const ulonglong2 wB = *(const ulonglong2*)(wp + 4);
                u64t* a = acc2[dy * 2 + dx];
                ffma2(a[0], v, wA.x);
                ffma2(a[1], v, wA.y);
                ffma2(a[2], v, wB.x);
                ffma2(a[3], v, wB.y);
            }
        }
        __syncthreads();
    }
#pragma unroll
    for (int dy = 0; dy < 2; dy++)
#pragma unroll
        for (int dx = 0; dx < 2; dx++) {
            const int oy = oy0 + 2 * sy + dy, ox = ox0 + 2 * sx + dx;
#pragma unroll
            for (int j = 0; j < 4; j++) {
                const int co = co0 + lane4 * 8 + 2 * j;
                const float2 pv = unpk(acc2[dy * 2 + dx][j]);
                float r0 = pv.x + bias[co];
                float r1 = pv.y + bias[co + 1];
                if (RELU) { r0 = fmaxf(r0, 0.f); r1 = fmaxf(r1, 0.f); }
                out[((n * Cout + co) * Hout + oy) * Wout + ox] = r0;
                out[((n * Cout + co + 1) * Hout + oy) * Wout + ox] = r1;
            }
        }
}

// ---------------------------------------------------------------------------
// ConvT small (Cout=3), cp.async double-buffered
// ---------------------------------------------------------------------------
__global__ __launch_bounds__(256) void convT4x4_small_kernel(
    const float* __restrict__ in, const float* __restrict__ w,
    const float* __restrict__ bias, float* __restrict__ out,
    int N, int Cin, int Hin, int Win) {
    const int Hout = Hin << 1, Wout = Win << 1;
    const int tid = threadIdx.x;
    const int sx = tid & 15, sy = tid >> 4;
    const int ox0 = blockIdx.x << 5, oy0 = blockIdx.y << 5;
    const int n = blockIdx.z;

    __shared__ float s_in[2][TCHNK][18][18];
    __shared__ float s_w[2][TCHNK][16][4];

    u64t acc01[4];
    float acc2s[4];
#pragma unroll
    for (int p = 0; p < 4; p++) { acc01[p] = 0ull; acc2s[p] = 0.f; }

    const int iy0 = (oy0 >> 1) - 1, ix0 = (ox0 >> 1) - 1;

    for (int idx = tid; idx < 2 * TCHNK * 324; idx += 256)
        ((float*)s_in)[idx] = 0.f;
    __syncthreads();

    auto load_chunk = [&](int ci0, int buf) {
        const int cc = min(TCHNK, Cin - ci0);
        for (int idx = tid; idx < cc * 324; idx += 256) {
            int c = idx / 324, r = idx - c * 324;
            int yy = r / 18, xx = r - yy * 18;
            int iy = iy0 + yy, ix = ix0 + xx;
            if ((unsigned)iy < (unsigned)Hin && (unsigned)ix < (unsigned)Win)
                cp_async4(&s_in[buf][c][yy][xx],
                          &in[((n * Cin + ci0 + c) * Hin + iy) * Win + ix]);
        }
        for (int idx = tid; idx < cc * 48; idx += 256) {
            int c = idx / 48, r = idx - c * 48;
            int co = r >> 4, kk = r & 15;
            cp_async4(&s_w[buf][c][kk][co], &w[(ci0 + c) * 3 * 16 + r]);
        }
        cp_commit();
    };

    const int nch = (Cin + TCHNK - 1) / TCHNK;
    load_chunk(0, 0);
    for (int it = 0; it < nch; it++) {
        const int buf = it & 1;
        if (it + 1 < nch) { load_chunk((it + 1) * TCHNK, buf ^ 1); cp_wait<1>(); }
        else cp_wait<0>();
        __syncthreads();
        const int cc = min(TCHNK, Cin - it * TCHNK);
        for (int c = 0; c < cc; c++) {
            float vin[3][3];
#pragma unroll
            for (int i = 0; i < 3; i++)
#pragma unroll
                for (int j2 = 0; j2 < 3; j2++) vin[i][j2] = s_in[buf][c][sy + i][sx + j2];
#pragma unroll
            for (int kk = 0; kk < 16; kk++) {
                const int ky = kk >> 2, kx = kk & 3;
                const int dy = (ky & 1) ? 0 : 1;
                const int ry = (ky & 1) ? (1 - ((ky - 1) >> 1)) : (2 - (ky >> 1));
                const int dx = (kx & 1) ? 0 : 1;
                const int rx = (kx & 1) ? (1 - ((kx - 1) >> 1)) : (2 - (kx >> 1));
                const float vs = vin[ry][rx];
                const u64t v = packdup(vs);
                const u64t w01 = *(const u64t*)&s_w[buf][c][kk][0];
                const int p = dy * 2 + dx;
                ffma2(acc01[p], v, w01);
                acc2s[p] = fmaf(vs, s_w[buf][c][kk][2], acc2s[p]);
            }
        }
        __syncthreads();
    }
#pragma unroll
    for (int dy = 0; dy < 2; dy++)
#pragma unroll
        for (int dx = 0; dx < 2; dx++) {
            const int oy = oy0 + 2 * sy + dy, ox = ox0 + 2 * sx + dx;
            const float2 pv = unpk(acc01[dy * 2 + dx]);
            out[((n * 3 + 0) * Hout + oy) * Wout + ox] = pv.x + bias[0];
            out[((n * 3 + 1) * Hout + oy) * Wout + ox] = pv.y + bias[1];
            out[((n * 3 + 2) * Hout + oy) * Wout + ox] = acc2s[dy * 2 + dx] + bias[2];
        }
}

// ---------------------------------------------------------------------------
// Fused 1x1 conv + VQ, f32x2, cp.async pipelined weight + codebook chunks
// ---------------------------------------------------------------------------
__global__ __launch_bounds__(256) void conv1x1_quantize_kernel(
    const float* __restrict__ inA, const float* __restrict__ inB, int CA, int CB,
    const float* __restrict__ w, const float* __restrict__ b,
    const float* __restrict__ embed, const float* __restrict__ norms,
    float* __restrict__ qout, float* __restrict__ idout, float* __restrict__ acc,
    int HW) {
    const int tid = threadIdx.x;
    const int v = blockIdx.x * 256 + tid;
    const int n = v / HW, hw = v - n * HW;
    const int Cin = CA + CB;

    __shared__ float s_w[2][16][68];
    __shared__ float s_e[2][128][68];
    __shared__ float s_n[2][128];

    u64t f2[32];
#pragma unroll
    for (int i = 0; i < 32; i++) f2[i] = 0ull;

    auto load_w = [&](int ci0, int buf) {
        for (int idx = tid; idx < 1024; idx += 256) {
            int c = idx & 15, co = idx >> 4;
            cp_async4(&s_w[buf][c][co], &w[co * Cin + ci0 + c]);
        }
        cp_commit();
    };

    const int nch = Cin >> 4;
    load_w(0, 0);
    for (int it = 0; it < nch; it++) {
        const int buf = it & 1;
        if (it + 1 < nch) { load_w((it + 1) * 16, buf ^ 1); cp_wait<1>(); }
        else cp_wait<0>();
        __syncthreads();
        const int ci0 = it * 16;
#pragma unroll 4
        for (int c = 0; c < 16; c++) {
            const int ci = ci0 + c;
            float val;
            if (ci < CA)
                val = inA[(n * CA + ci) * HW + hw];
            else
                val = inB[(n * CB + (ci - CA)) * HW + hw];
            const u64t vp = packdup(val);
            const ulonglong2* wr = (const ulonglong2*)s_w[buf][c];
#pragma unroll
            for (int j = 0; j < 16; j++) {
                const ulonglong2 wv = wr[j];
                ffma2(f2[2 * j + 0], vp, wv.x);
                ffma2(f2[2 * j + 1], vp, wv.y);
            }
        }
        __syncthreads();
    }
    // bias
    float f[64];
#pragma unroll
    for (int i = 0; i < 32; i++) {
        const float2 pv = unpk(f2[i]);
        f[2 * i] = pv.x + b[2 * i];
        f[2 * i + 1] = pv.y + b[2 * i + 1];
        f2[i] = pack2(f[2 * i], f[2 * i + 1]);
    }

    auto load_e = [&](int k0, int buf) {
        for (int idx = tid; idx < 8192; idx += 256) {
            int d = idx >> 7, k = idx & 127;
            cp_async4(&s_e[buf][k][d], &embed[d * 512 + k0 + k]);
        }
        if (tid < 128) cp_async4(&s_n[buf][tid], &norms[k0 + tid]);
        cp_commit();
    };

    float best = 3.4e38f;
    int bid = 0;
    load_e(0, 0);
    for (int it = 0; it < 4; it++) {
        const int buf = it & 1;
        if (it + 1 < 4) { load_e((it + 1) * 128, buf ^ 1); cp_wait<1>(); }
        else cp_wait<0>();
        __syncthreads();
        const int k0 = it * 128;
        for (int k = 0; k < 128; k++) {
            u64t d0 = 0ull, d1 = 0ull;
            const ulonglong2* er = (const ulonglong2*)s_e[buf][k];
#pragma unroll
            for (int j = 0; j < 16; j++) {
                const ulonglong2 e = er[j];
                ffma2(d0, f2[2 * j + 0], e.x);
                ffma2(d1, f2[2 * j + 1], e.y);
            }
            const float2 a0 = unpk(d0), a1 = unpk(d1);
            const float sc = s_n[buf][k] - 2.f * ((a0.x + a0.y) + (a1.x + a1.y));
            if (sc < best) { best = sc; bid = k0 + k; }
        }
        __syncthreads();
    }

    float lsum = 0.f;
#pragma unroll
    for (int d = 0; d < 64; d++) {
        const float q = __ldg(&embed[d * 512 + bid]);
        const float df = q - f[d];
        lsum = fmaf(df, df, lsum);
        qout[(n * 64 + d) * HW + hw] = q;
    }
    idout[v] = (float)bid;
#pragma unroll
    for (int o = 16; o > 0; o >>= 1) lsum += __shfl_down_sync(0xffffffffu, lsum, o);
    if ((tid & 31) == 0) atomicAdd(acc, lsum);
}

__global__ void finalize_loss_kernel(const float* __restrict__ acc, float* __restrict__ o) {
    o[0] = acc[0] * (1.f / 1048576.f) + acc[1] * (1.f / 4194304.f);
}

extern "C" void kernel_launch(void* const* d_in, const int* in_sizes, int n_in,
                              void* d_out, int out_size) {
    (void)in_sizes; (void)n_in; (void)out_size;
    const float* x       = (const float*)d_in[0];
    const float* wb1     = (const float*)d_in[1];
    const float* bb1     = (const float*)d_in[2];
    const float* wb2     = (const float*)d_in[3];
    const float* bb2     = (const float*)d_in[4];
    const float* wt1     = (const float*)d_in[5];
    const float* bt1     = (const float*)d_in[6];
    const float* wqt     = (const float*)d_in[7];
    const float* bqt     = (const float*)d_in[8];
    const float* embed_t = (const float*)d_in[9];
    const float* wdt     = (const float*)d_in[10];
    const float* bdt     = (const float*)d_in[11];
    const float* wqb     = (const float*)d_in[12];
    const float* bqb     = (const float*)d_in[13];
    const float* embed_b = (const float*)d_in[14];
    const float* wup     = (const float*)d_in[15];
    const float* bup     = (const float*)d_in[16];
    const float* wd1     = (const float*)d_in[17];
    const float* bd1     = (const float*)d_in[18];
    const float* wd2     = (const float*)d_in[19];
    const float* bd2     = (const float*)d_in[20];

    float* out    = (float*)d_out;
    float* o_xhat = out;
    float* o_qt   = out + 3145728;
    float* o_qb   = out + 4194304;
    float* o_loss = out + 8388608;
    float* o_idt  = out + 8388609;
    float* o_idb  = out + 8404993;

    float *encb1, *encb, *enct, *dect, *upt, *h, *normt, *normb, *acc;
    cudaGetSymbolAddress((void**)&encb1, g_encb1);
    cudaGetSymbolAddress((void**)&encb,  g_encb);
    cudaGetSymbolAddress((void**)&enct,  g_enct);
    cudaGetSymbolAddress((void**)&dect,  g_dect);
    cudaGetSymbolAddress((void**)&upt,   g_upt);
    cudaGetSymbolAddress((void**)&h,     g_h);
    cudaGetSymbolAddress((void**)&normt, g_normt);
    cudaGetSymbolAddress((void**)&normb, g_normb);
    cudaGetSymbolAddress((void**)&acc,   g_acc);

    init_kernel<<<1, 512>>>(embed_t, embed_b, normt, normb, acc);

    conv4x4s2_kernel<true><<<dim3(8, 8, 16 * 4), 256>>>(x, wb1, bb1, encb1, 16, 3, 128, 256, 256);
    conv4x4s2_kernel<true><<<dim3(4, 4, 16 * 4), 256>>>(encb1, wb2, bb2, encb, 16, 128, 128, 128, 128);
    conv4x4s2_kernel<true><<<dim3(2, 2, 16 * 4), 256>>>(encb, wt1, bt1, enct, 16, 128, 128, 64, 64);

    conv1x1_quantize_kernel<<<16384 / 256, 256>>>(enct, enct, 128, 0, wqt, bqt,
                                                  embed_t, normt, o_qt, o_idt, acc + 0, 1024);

    convT4x4_kernel<false><<<dim3(4, 4, 16 * 2), 256>>>(o_qt, o_qt, 64, wdt, bdt, dect, 16, 64, 64, 32, 32);
    conv1x1_quantize_kernel<<<65536 / 256, 256>>>(dect, encb, 64, 128, wqb, bqb,
                                                  embed_b, normb, o_qb, o_idb, acc + 1, 4096);

    convT4x4_kernel<false><<<dim3(4, 4, 16 * 2), 256>>>(o_qt, o_qt, 64, wup, bup, upt, 16, 64, 64, 32, 32);
    convT4x4_kernel<true><<<dim3(8, 8, 16 * 2), 256>>>(upt, o_qb, 64, wd1, bd1, h, 16, 128, 64, 64, 64);
    convT4x4_small_kernel<<<dim3(8, 8, 16), 256>>>(h, wd2, bd2, o_xhat, 16, 64, 128, 128);

    finalize_loss_kernel<<<1, 1>>>(acc, o_loss);
}

// round 6
// speedup vs baseline: 1.6157x; 1.0088x over previous
#include <cuda_runtime.h>
#include <cuda_bf16.h>

typedef unsigned long long u64t;

__device__ __forceinline__ void ffma2(u64t& d, u64t a, u64t b) {
    asm("fma.rn.f32x2 %0, %1, %2, %0;" : "+l"(d) : "l"(a), "l"(b));
}
__device__ __forceinline__ u64t packdup(float v) {
    u64t r;
    asm("mov.b64 %0, {%1, %1};" : "=l"(r) : "r"(__float_as_uint(v)));
    return r;
}
__device__ __forceinline__ u64t pack2(float a, float b) {
    u64t r;
    asm("mov.b64 %0, {%1, %2};" : "=l"(r) : "r"(__float_as_uint(a)), "r"(__float_as_uint(b)));
    return r;
}
__device__ __forceinline__ float2 unpk(u64t p) {
    unsigned lo, hi;
    asm("mov.b64 {%0, %1}, %2;" : "=r"(lo), "=r"(hi) : "l"(p));
    return make_float2(__uint_as_float(lo), __uint_as_float(hi));
}
__device__ __forceinline__ void cp_async4(void* smem, const void* gmem) {
    unsigned s = (unsigned)__cvta_generic_to_shared(smem);
    asm volatile("cp.async.ca.shared.global [%0], [%1], 4;" :: "r"(s), "l"(gmem));
}
__device__ __forceinline__ void cp_commit() {
    asm volatile("cp.async.commit_group;" ::: "memory");
}
template <int N>
__device__ __forceinline__ void cp_wait() {
    asm volatile("cp.async.wait_group %0;" :: "n"(N) : "memory");
}

__device__ float g_encb1[16 * 128 * 128 * 128];
__device__ float g_encb [16 * 128 * 64 * 64];
__device__ float g_enct [2 * 16 * 128 * 32 * 32];   // split-K partials for conv3
__device__ float g_dect [16 * 64 * 64 * 64];
__device__ float g_upt  [16 * 64 * 64 * 64];
__device__ float g_h    [16 * 64 * 128 * 128];
__device__ float g_normt[512];
__device__ float g_normb[512];
__device__ float g_acc[2];

__global__ void init_kernel(const float* __restrict__ et, const float* __restrict__ eb,
                            float* __restrict__ nt, float* __restrict__ nb,
                            float* __restrict__ acc) {
    int k = threadIdx.x; // 512 threads
    float st = 0.f, sb = 0.f;
#pragma unroll
    for (int d = 0; d < 64; d++) {
        float a = et[d * 512 + k]; st = fmaf(a, a, st);
        float b = eb[d * 512 + k]; sb = fmaf(b, b, sb);
    }
    nt[k] = st;
    nb[k] = sb;
    if (k < 2) acc[k] = 0.f;
}

// ---------------------------------------------------------------------------
// 4x4 stride-2 pad-1 conv (+relu), f32x2 math, cp.async double-buffered.
// KS: split-K factor. KS>1 => no bias/relu, partial-k output at
// out + ks*N*Cout*Hout*Wout. Grid z = N * (Cout/32) * KS.
// ---------------------------------------------------------------------------
#define CCHNK 4
template <bool RELU, int KS>
__global__ __launch_bounds__(256, 3) void conv4x4s2_kernel(
    const float* __restrict__ in, const float* __restrict__ w,
    const float* __restrict__ bias, float* __restrict__ out,
    int N, int Cin, int Cout, int Hin, int Win) {
    const int Hout = Hin >> 1, Wout = Win >> 1;
    const int tid = threadIdx.x;
    const int lane4 = tid & 3;
    const int sp = tid >> 2;
    const int sx = sp & 7, sy = sp >> 3;
    const int ox0 = blockIdx.x << 4, oy0 = blockIdx.y << 4;
    const int cog = Cout >> 5;
    const int zdiv = cog * KS;
    const int n = blockIdx.z / zdiv;
    const int rem = blockIdx.z % zdiv;
    const int ks = rem / cog;
    const int co0 = (rem % cog) << 5;
    const int CinL = Cin / KS;
    const int ciBase = ks * CinL;
    float* outp = out + (size_t)ks * N * Cout * Hout * Wout;

    __shared__ float s_in[2][CCHNK][34][34];
    __shared__ float s_w[2][CCHNK][16][36];

    u64t acc2[4][4];
#pragma unroll
    for (int p = 0; p < 4; p++)
#pragma unroll
        for (int j = 0; j < 4; j++) acc2[p][j] = 0ull;

    const int iyb = 2 * oy0 - 1, ixb = 2 * ox0 - 1;
    const int by = 4 * sy, bx = 4 * sx;

    for (int idx = tid; idx < 2 * CCHNK * 1156; idx += 256)
        ((float*)s_in)[idx] = 0.f;
    __syncthreads();

    auto load_chunk = [&](int ci0, int buf) {
        const int cc = min(CCHNK, CinL - ci0);
        for (int idx = tid; idx < cc * 1156; idx += 256) {
            int c = idx / 1156, r = idx - c * 1156;
            int yy = r / 34, xx = r - yy * 34;
            int iy = iyb + yy, ix = ixb + xx;
            if ((unsigned)iy < (unsigned)Hin && (unsigned)ix < (unsigned)Win)
                cp_async4(&s_in[buf][c][yy][xx],
                          &in[((n * Cin + ciBase + ci0 + c) * Hin + iy) * Win + ix]);
        }
        const int cseg = cc * 16;
        for (int idx = tid; idx < cc * 512; idx += 256) {
            int co = idx / cseg;
            int r = idx - co * cseg;
            int c = r >> 4, kk = r & 15;
            cp_async4(&s_w[buf][c][kk][co],
                      &w[(co0 + co) * Cin * 16 + (ciBase + ci0) * 16 + r]);
        }
        cp_commit();
    };

    const int nch = (CinL + CCHNK - 1) / CCHNK;
    load_chunk(0, 0);
    for (int it = 0; it < nch; it++) {
        const int buf = it & 1;
        if (it + 1 < nch) { load_chunk((it + 1) * CCHNK, buf ^ 1); cp_wait<1>(); }
        else cp_wait<0>();
        __syncthreads();
        const int cc = min(CCHNK, CinL - it * CCHNK);
        for (int c = 0; c < cc; c++) {
#pragma unroll
            for (int kk = 0; kk < 16; kk++) {
                const int ky = kk >> 2, kx = kk & 3;
                const u64t v00 = packdup(s_in[buf][c][by + ky][bx + kx]);
                const u64t v01 = packdup(s_in[buf][c][by + ky][bx + kx + 2]);
                const u64t v10 = packdup(s_in[buf][c][by + ky + 2][bx + kx]);
                const u64t v11 = packdup(s_in[buf][c][by + ky + 2][bx + kx + 2]);
                const float* wp = &s_w[buf][c][kk][lane4 * 8];
                const ulonglong2 wA = *(const ulonglong2*)(wp);
                const ulonglong2 wB = *(const ulonglong2*)(wp + 4);
                ffma2(acc2[0][0], v00, wA.x); ffma2(acc2[0][1], v00, wA.y);
                ffma2(acc2[0][2], v00, wB.x); ffma2(acc2[0][3], v00, wB.y);
                ffma2(acc2[1][0], v01, wA.x); ffma2(acc2[1][1], v01, wA.y);
                ffma2(acc2[1][2], v01, wB.x); ffma2(acc2[1][3], v01, wB.y);
                ffma2(acc2[2][0], v10, wA.x); ffma2(acc2[2][1], v10, wA.y);
                ffma2(acc2[2][2], v10, wB.x); ffma2(acc2[2][3], v10, wB.y);
                ffma2(acc2[3][0], v11, wA.x); ffma2(acc2[3][1], v11, wA.y);
                ffma2(acc2[3][2], v11, wB.x); ffma2(acc2[3][3], v11, wB.y);
            }
        }
        __syncthreads();
    }
#pragma unroll
    for (int dy = 0; dy < 2; dy++)
#pragma unroll
        for (int dx = 0; dx < 2; dx++) {
            const int oy = oy0 + 2 * sy + dy, ox = ox0 + 2 * sx + dx;
#pragma unroll
            for (int j = 0; j < 4; j++) {
                const int co = co0 + lane4 * 8 + 2 * j;
                const float2 pv = unpk(acc2[dy * 2 + dx][j]);
                float r0 = pv.x, r1 = pv.y;
                if (KS == 1) { r0 += bias[co]; r1 += bias[co + 1]; }
                if (RELU) { r0 = fmaxf(r0, 0.f); r1 = fmaxf(r1, 0.f); }
                outp[((n * Cout + co) * Hout + oy) * Wout + ox] = r0;
                outp[((n * Cout + co + 1) * Hout + oy) * Wout + ox] = r1;
            }
        }
}

// ---------------------------------------------------------------------------
// convT, f32x2, cp.async double-buffered. DUAL: two weight/bias/output sets
// sharing the same input (dect + upt fusion); grid z doubles.
// ---------------------------------------------------------------------------
#define TCHNK 8
template <bool RELU, bool DUAL>
__global__ __launch_bounds__(256, 3) void convT4x4_kernel(
    const float* __restrict__ inA, const float* __restrict__ inB, int CA,
    const float* __restrict__ w, const float* __restrict__ bias,
    float* __restrict__ out,
    const float* __restrict__ w2, const float* __restrict__ bias2,
    float* __restrict__ out2,
    int N, int Cin, int Cout, int Hin, int Win) {
    const int Hout = Hin << 1, Wout = Win << 1;
    const int tid = threadIdx.x;
    const int lane4 = tid & 3;
    const int sp = tid >> 2;
    const int sx = sp & 7, sy = sp >> 3;
    const int ox0 = blockIdx.x << 4, oy0 = blockIdx.y << 4;
    const int cog = Cout >> 5;
    const int zdiv = cog * (DUAL ? 2 : 1);
    const int n = blockIdx.z / zdiv;
    int g = blockIdx.z % zdiv;
    const float* wU = w;
    const float* bU = bias;
    float* oU = out;
    if (DUAL && g >= cog) { wU = w2; bU = bias2; oU = out2; g -= cog; }
    const int co0 = g << 5;
    const int CB = Cin - CA;

    __shared__ float s_in[2][TCHNK][10][10];
    __shared__ float s_w[2][TCHNK][16][36];

    u64t acc2[4][4];
#pragma unroll
    for (int p = 0; p < 4; p++)
#pragma unroll
        for (int j = 0; j < 4; j++) acc2[p][j] = 0ull;

    const int iy0 = (oy0 >> 1) - 1, ix0 = (ox0 >> 1) - 1;

    for (int idx = tid; idx < 2 * TCHNK * 100; idx += 256)
        ((float*)s_in)[idx] = 0.f;
    __syncthreads();

    auto load_chunk = [&](int ci0, int buf) {
        const int cc = min(TCHNK, Cin - ci0);
        for (int idx = tid; idx < cc * 100; idx += 256) {
            int c = idx / 100, r = idx - c * 100;
            int yy = r / 10, xx = r - yy * 10;
            int iy = iy0 + yy, ix = ix0 + xx;
            int ci = ci0 + c;
            if ((unsigned)iy < (unsigned)Hin && (unsigned)ix < (unsigned)Win) {
                const float* src = (ci < CA)
                    ? &inA[((n * CA + ci) * Hin + iy) * Win + ix]
                    : &inB[((n * CB + (ci - CA)) * Hin + iy) * Win + ix];
                cp_async4(&s_in[buf][c][yy][xx], src);
            }
        }
        for (int idx = tid; idx < cc * 512; idx += 256) {
            int c = idx >> 9, r = idx & 511;
            int co = r >> 4, kk = r & 15;
            cp_async4(&s_w[buf][c][kk][co], &wU[(ci0 + c) * Cout * 16 + co0 * 16 + r]);
        }
        cp_commit();
    };

    const int nch = (Cin + TCHNK - 1) / TCHNK;
    load_chunk(0, 0);
    for (int it = 0; it < nch; it++) {
        const int buf = it & 1;
        if (it + 1 < nch) { load_chunk((it + 1) * TCHNK, buf ^ 1); cp_wait<1>(); }
        else cp_wait<0>();
        __syncthreads();
        const int cc = min(TCHNK, Cin - it * TCHNK);
        for (int c = 0; c < cc; c++) {
            u64t vin[3][3];
#pragma unroll
            for (int i = 0; i < 3; i++)
#pragma unroll
                for (int j2 = 0; j2 < 3; j2++) vin[i][j2] = packdup(s_in[buf][c][sy + i][sx + j2]);
#pragma unroll
            for (int kk = 0; kk < 16; kk++) {
                const int ky = kk >> 2, kx = kk & 3;
                const int dy = (ky & 1) ? 0 : 1;
                const int ry = (ky & 1) ? (1 - ((ky - 1) >> 1)) : (2 - (ky >> 1));
                const int dx = (kx & 1) ? 0 : 1;
                const int rx = (kx & 1) ? (1 - ((kx - 1) >> 1)) : (2 - (kx >> 1));
                const u64t v = vin[ry][rx];
                const float* wp = &s_w[buf][c][kk][lane4 * 8];
                const ulonglong2 wA = *(const ulonglong2*)(wp);
                const ulonglong2 wB = *(const ulonglong2*)(wp + 4);
                u64t* a = acc2[dy * 2 + dx];
                ffma2(a[0], v, wA.x);
                ffma2(a[1], v, wA.y);
                ffma2(a[2], v, wB.x);
                ffma2(a[3], v, wB.y);
            }
        }
        __syncthreads();
    }
#pragma unroll
    for (int dy = 0; dy < 2; dy++)
#pragma unroll
        for (int dx = 0; dx < 2; dx++) {
            const int oy = oy0 + 2 * sy + dy, ox = ox0 + 2 * sx + dx;
#pragma unroll
            for (int j = 0; j < 4; j++) {
                const int co = co0 + lane4 * 8 + 2 * j;
                const float2 pv = unpk(acc2[dy * 2 + dx][j]);
                float r0 = pv.x + bU[co];
                float r1 = pv.y + bU[co + 1];
                if (RELU) { r0 = fmaxf(r0, 0.f); r1 = fmaxf(r1, 0.f); }
                oU[((n * Cout + co) * Hout + oy) * Wout + ox] = r0;
                oU[((n * Cout + co + 1) * Hout + oy) * Wout + ox] = r1;
            }
        }
}

// ---------------------------------------------------------------------------
// ConvT small (Cout=3), cp.async double-buffered
// ---------------------------------------------------------------------------
__global__ __launch_bounds__(256) void convT4x4_small_kernel(
    const float* __restrict__ in, const float* __restrict__ w,
    const float* __restrict__ bias, float* __restrict__ out,
    int N, int Cin, int Hin, int Win) {
    const int Hout = Hin << 1, Wout = Win << 1;
    const int tid = threadIdx.x;
    const int sx = tid & 15, sy = tid >> 4;
    const int ox0 = blockIdx.x << 5, oy0 = blockIdx.y << 5;
    const int n = blockIdx.z;

    __shared__ float s_in[2][TCHNK][18][18];
    __shared__ float s_w[2][TCHNK][16][4];

    u64t acc01[4];
    float acc2s[4];
#pragma unroll
    for (int p = 0; p < 4; p++) { acc01[p] = 0ull; acc2s[p] = 0.f; }

    const int iy0 = (oy0 >> 1) - 1, ix0 = (ox0 >> 1) - 1;

    for (int idx = tid; idx < 2 * TCHNK * 324; idx += 256)
        ((float*)s_in)[idx] = 0.f;
    __syncthreads();

    auto load_chunk = [&](int ci0, int buf) {
        const int cc = min(TCHNK, Cin - ci0);
        for (int idx = tid; idx < cc * 324; idx += 256) {
            int c = idx / 324, r = idx - c * 324;
            int yy = r / 18, xx = r - yy * 18;
            int iy = iy0 + yy, ix = ix0 + xx;
            if ((unsigned)iy < (unsigned)Hin && (unsigned)ix < (unsigned)Win)
                cp_async4(&s_in[buf][c][yy][xx],
                          &in[((n * Cin + ci0 + c) * Hin + iy) * Win + ix]);
        }
        for (int idx = tid; idx < cc * 48; idx += 256) {
            int c = idx / 48, r = idx - c * 48;
            int co = r >> 4, kk = r & 15;
            cp_async4(&s_w[buf][c][kk][co], &w[(ci0 + c) * 3 * 16 + r]);
        }
        cp_commit();
    };

    const int nch = (Cin + TCHNK - 1) / TCHNK;
    load_chunk(0, 0);
    for (int it = 0; it < nch; it++) {
        const int buf = it & 1;
        if (it + 1 < nch) { load_chunk((it + 1) * TCHNK, buf ^ 1); cp_wait<1>(); }
        else cp_wait<0>();
        __syncthreads();
        const int cc = min(TCHNK, Cin - it * TCHNK);
        for (int c = 0; c < cc; c++) {
            float vin[3][3];
#pragma unroll
            for (int i = 0; i < 3; i++)
#pragma unroll
                for (int j2 = 0; j2 < 3; j2++) vin[i][j2] = s_in[buf][c][sy + i][sx + j2];
#pragma unroll
            for (int kk = 0; kk < 16; kk++) {
                const int ky = kk >> 2, kx = kk & 3;
                const int dy = (ky & 1) ? 0 : 1;
                const int ry = (ky & 1) ? (1 - ((ky - 1) >> 1)) : (2 - (ky >> 1));
                const int dx = (kx & 1) ? 0 : 1;
                const int rx = (kx & 1) ? (1 - ((kx - 1) >> 1)) : (2 - (kx >> 1));
                const float vs = vin[ry][rx];
                const u64t v = packdup(vs);
                const u64t w01 = *(const u64t*)&s_w[buf][c][kk][0];
                const int p = dy * 2 + dx;
                ffma2(acc01[p], v, w01);
                acc2s[p] = fmaf(vs, s_w[buf][c][kk][2], acc2s[p]);
            }
        }
        __syncthreads();
    }
#pragma unroll
    for (int dy = 0; dy < 2; dy++)
#pragma unroll
        for (int dx = 0; dx < 2; dx++) {
            const int oy = oy0 + 2 * sy + dy, ox = ox0 + 2 * sx + dx;
            const float2 pv = unpk(acc01[dy * 2 + dx]);
            out[((n * 3 + 0) * Hout + oy) * Wout + ox] = pv.x + bias[0];
            out[((n * 3 + 1) * Hout + oy) * Wout + ox] = pv.y + bias[1];
            out[((n * 3 + 2) * Hout + oy) * Wout + ox] = acc2s[dy * 2 + dx] + bias[2];
        }
}

// ---------------------------------------------------------------------------
// Fused 1x1 conv + VQ. 128 threads/block, 64-wide codebook chunks.
// MODE 0: input = concat(inA[CA], inB[CB]).
// MODE 1: input channel ci = relu(inA[ci] + inB[ci] + cbias[ci]) (split-K sum),
//         Cin = CA.
// ---------------------------------------------------------------------------
template <int MODE>
__global__ __launch_bounds__(128) void conv1x1_quantize_kernel(
    const float* __restrict__ inA, const float* __restrict__ inB, int CA, int CB,
    const float* __restrict__ cbias,
    const float* __restrict__ w, const float* __restrict__ b,
    const float* __restrict__ embed, const float* __restrict__ norms,
    float* __restrict__ qout, float* __restrict__ idout, float* __restrict__ acc,
    int HW) {
    const int tid = threadIdx.x;
    const int v = blockIdx.x * 128 + tid;
    const int n = v / HW, hw = v - n * HW;
    const int Cin = (MODE == 0) ? (CA + CB) : CA;

    __shared__ float s_w[2][16][68];
    __shared__ float s_e[2][64][68];
    __shared__ float s_n[2][64];

    u64t f2[32];
#pragma unroll
    for (int i = 0; i < 32; i++) f2[i] = 0ull;

    auto load_w = [&](int ci0, int buf) {
        for (int idx = tid; idx < 1024; idx += 128) {
            int c = idx & 15, co = idx >> 4;
            cp_async4(&s_w[buf][c][co], &w[co * Cin + ci0 + c]);
        }
        cp_commit();
    };

    const int nch = Cin >> 4;
    load_w(0, 0);
    for (int it = 0; it < nch; it++) {
        const int buf = it & 1;
        if (it + 1 < nch) { load_w((it + 1) * 16, buf ^ 1); cp_wait<1>(); }
        else cp_wait<0>();
        __syncthreads();
        const int ci0 = it * 16;
#pragma unroll 4
        for (int c = 0; c < 16; c++) {
            const int ci = ci0 + c;
            float val;
            if (MODE == 0) {
                if (ci < CA)
                    val = inA[(n * CA + ci) * HW + hw];
                else
                    val = inB[(n * CB + (ci - CA)) * HW + hw];
            } else {
                const int off = (n * CA + ci) * HW + hw;
                val = fmaxf(inA[off] + inB[off] + __ldg(&cbias[ci]), 0.f);
            }
            const u64t vp = packdup(val);
            const ulonglong2* wr = (const ulonglong2*)s_w[buf][c];
#pragma unroll
            for (int j = 0; j < 16; j++) {
                const ulonglong2 wv = wr[j];
                ffma2(f2[2 * j + 0], vp, wv.x);
                ffma2(f2[2 * j + 1], vp, wv.y);
            }
        }
        __syncthreads();
    }
    // bias
    float f[64];
#pragma unroll
    for (int i = 0; i < 32; i++) {
        const float2 pv = unpk(f2[i]);
        f[2 * i] = pv.x + b[2 * i];
        f[2 * i + 1] = pv.y + b[2 * i + 1];
        f2[i] = pack2(f[2 * i], f[2 * i + 1]);
    }

    auto load_e = [&](int k0, int buf) {
        for (int idx = tid; idx < 4096; idx += 128) {
            int d = idx >> 6, k = idx & 63;
            cp_async4(&s_e[buf][k][d], &embed[d * 512 + k0 + k]);
        }
        if (tid < 64) cp_async4(&s_n[buf][tid], &norms[k0 + tid]);
        cp_commit();
    };

    float best = 3.4e38f;
    int bid = 0;
    load_e(0, 0);
    for (int it = 0; it < 8; it++) {
        const int buf = it & 1;
        if (it + 1 < 8) { load_e((it + 1) * 64, buf ^ 1); cp_wait<1>(); }
        else cp_wait<0>();
        __syncthreads();
        const int k0 = it * 64;
        for (int k = 0; k < 64; k++) {
            u64t d0 = 0ull, d1 = 0ull;
            const ulonglong2* er = (const ulonglong2*)s_e[buf][k];
#pragma unroll
            for (int j = 0; j < 16; j++) {
                const ulonglong2 e = er[j];
                ffma2(d0, f2[2 * j + 0], e.x);
                ffma2(d1, f2[2 * j + 1], e.y);
            }
            const float2 a0 = unpk(d0), a1 = unpk(d1);
            const float sc = s_n[buf][k] - 2.f * ((a0.x + a0.y) + (a1.x + a1.y));
            if (sc < best) { best = sc; bid = k0 + k; }
        }
        __syncthreads();
    }

    float lsum = 0.f;
#pragma unroll
    for (int d = 0; d < 64; d++) {
        const float q = __ldg(&embed[d * 512 + bid]);
        const float df = q - f[d];
        lsum = fmaf(df, df, lsum);
        qout[(n * 64 + d) * HW + hw] = q;
    }
    idout[v] = (float)bid;
#pragma unroll
    for (int o = 16; o > 0; o >>= 1) lsum += __shfl_down_sync(0xffffffffu, lsum, o);
    if ((tid & 31) == 0) atomicAdd(acc, lsum);
}

__global__ void finalize_loss_kernel(const float* __restrict__ acc, float* __restrict__ o) {
    o[0] = acc[0] * (1.f / 1048576.f) + acc[1] * (1.f / 4194304.f);
}

extern "C" void kernel_launch(void* const* d_in, const int* in_sizes, int n_in,
                              void* d_out, int out_size) {
    (void)in_sizes; (void)n_in; (void)out_size;
    const float* x       = (const float*)d_in[0];
    const float* wb1     = (const float*)d_in[1];
    const float* bb1     = (const float*)d_in[2];
    const float* wb2     = (const float*)d_in[3];
    const float* bb2     = (const float*)d_in[4];
    const float* wt1     = (const float*)d_in[5];
    const float* bt1     = (const float*)d_in[6];
    const float* wqt     = (const float*)d_in[7];
    const float* bqt     = (const float*)d_in[8];
    const float* embed_t = (const float*)d_in[9];
    const float* wdt     = (const float*)d_in[10];
    const float* bdt     = (const float*)d_in[11];
    const float* wqb     = (const float*)d_in[12];
    const float* bqb     = (const float*)d_in[13];
    const float* embed_b = (const float*)d_in[14];
    const float* wup     = (const float*)d_in[15];
    const float* bup     = (const float*)d_in[16];
    const float* wd1     = (const float*)d_in[17];
    const float* bd1     = (const float*)d_in[18];
    const float* wd2     = (const float*)d_in[19];
    const float* bd2     = (const float*)d_in[20];

    float* out    = (float*)d_out;
    float* o_xhat = out;
    float* o_qt   = out + 3145728;
    float* o_qb   = out + 4194304;
    float* o_loss = out + 8388608;
    float* o_idt  = out + 8388609;
    float* o_idb  = out + 8404993;

    float *encb1, *encb, *enct, *dect, *upt, *h, *normt, *normb, *acc;
    cudaGetSymbolAddress((void**)&encb1, g_encb1);
    cudaGetSymbolAddress((void**)&encb,  g_encb);
    cudaGetSymbolAddress((void**)&enct,  g_enct);
    cudaGetSymbolAddress((void**)&dect,  g_dect);
    cudaGetSymbolAddress((void**)&upt,   g_upt);
    cudaGetSymbolAddress((void**)&h,     g_h);
    cudaGetSymbolAddress((void**)&normt, g_normt);
    cudaGetSymbolAddress((void**)&normb, g_normb);
    cudaGetSymbolAddress((void**)&acc,   g_acc);

    init_kernel<<<1, 512>>>(embed_t, embed_b, normt, normb, acc);

    // ---- encoder ----
    conv4x4s2_kernel<true, 1><<<dim3(8, 8, 16 * 4), 256>>>(x, wb1, bb1, encb1, 16, 3, 128, 256, 256);
    conv4x4s2_kernel<true, 1><<<dim3(4, 4, 16 * 4), 256>>>(encb1, wb2, bb2, encb, 16, 128, 128, 128, 128);
    // conv3: split-K x2 -> partials; bias+relu fused into quant_t input
    conv4x4s2_kernel<false, 2><<<dim3(2, 2, 16 * 4 * 2), 256>>>(encb, wt1, nullptr, enct, 16, 128, 128, 64, 64);

    // ---- top quantize (reads relu(p0+p1+bt1)) ----
    conv1x1_quantize_kernel<1><<<16384 / 128, 128>>>(enct, enct + 2097152, 128, 0, bt1,
                                                     wqt, bqt, embed_t, normt, o_qt, o_idt, acc + 0, 1024);

    // ---- decoder_top + upsample_t fused (both read quant_t) ----
    convT4x4_kernel<false, true><<<dim3(4, 4, 16 * 4), 256>>>(
        o_qt, o_qt, 64, wdt, bdt, dect, wup, bup, upt, 16, 64, 64, 32, 32);

    // ---- bottom quantize ----
    conv1x1_quantize_kernel<0><<<65536 / 128, 128>>>(dect, encb, 64, 128, nullptr,
                                                     wqb, bqb, embed_b, normb, o_qb, o_idb, acc + 1, 4096);

    // ---- decode ----
    convT4x4_kernel<true, false><<<dim3(8, 8, 16 * 2), 256>>>(
        upt, o_qb, 64, wd1, bd1, h, nullptr, nullptr, nullptr, 16, 128, 64, 64, 64);
    convT4x4_small_kernel<<<dim3(8, 8, 16), 256>>>(h, wd2, bd2, o_xhat, 16, 64, 128, 128);

    finalize_loss_kernel<<<1, 1>>>(acc, o_loss);
}